// round 1
// baseline (speedup 1.0000x reference)
#include <cuda_runtime.h>
#include <cuda_bf16.h>
#include <cstdint>

// ---------------- problem constants ----------------
#define D_MODEL   1024
#define D_STATE   64
#define D_CONV    4
#define HEADDIM   64
#define D_INNER   2048
#define NHEADS    32
#define CONV_DIM  2176            // D_INNER + 2*D_STATE
#define D_IN_PROJ 4256            // 2*D_INNER + 2*D_STATE + NHEADS
#define B_SZ      4
#define SEQLEN    2048
#define ROWS      (B_SZ * SEQLEN) // 8192

// ---------------- scratch (static device memory; no runtime alloc) ----------------
__device__ float g_zx[(size_t)ROWS * D_IN_PROJ];   // u @ W_in
__device__ float g_conv[(size_t)ROWS * CONV_DIM];  // conv+silu output
__device__ float g_dt[(size_t)ROWS * NHEADS];
__device__ float g_dA[(size_t)ROWS * NHEADS];
__device__ float g_y[(size_t)ROWS * D_INNER];      // scan output (+ x*D)
__device__ float g_yn[(size_t)ROWS * D_INNER];     // gated + rmsnormed

// ---------------- tiled FP32 GEMM: C[M,N] = A[M,K] @ B[K,N] ----------------
// BM=BN=128, BK=8, 8x8 per thread, 256 threads. Requires M%128==0, K%8==0, N%4==0.
#define GBM 128
#define GBN 128
#define GBK 8
#define GTM 8
#define GTN 8

__global__ __launch_bounds__(256) void sgemm128(
    const float* __restrict__ A, const float* __restrict__ B,
    float* __restrict__ C, int M, int N, int K)
{
    __shared__ float As[GBK][GBM];
    __shared__ float Bs[GBK][GBN];

    const int tid  = threadIdx.x;
    const int cRow = blockIdx.y;
    const int cCol = blockIdx.x;
    const int trow = tid >> 4;        // 0..15
    const int tcol = tid & 15;        // 0..15

    const int aRow  = tid >> 1;       // 0..127
    const int aCol4 = (tid & 1) * 4;  // 0 or 4
    const int bRow  = tid >> 5;       // 0..7
    const int bCol4 = (tid & 31) * 4; // 0..124

    const float* Ab = A + (size_t)(cRow * GBM) * K;
    const float* Bb = B + (size_t)(cCol * GBN);

    const int gBcol = cCol * GBN + bCol4;
    const bool bOk  = (gBcol < N);    // N%4==0 && col%4==0 -> col+3 < N

    float acc[GTM][GTN];
    #pragma unroll
    for (int m = 0; m < GTM; m++)
        #pragma unroll
        for (int n = 0; n < GTN; n++) acc[m][n] = 0.f;

    for (int k0 = 0; k0 < K; k0 += GBK) {
        float4 av = *reinterpret_cast<const float4*>(Ab + (size_t)aRow * K + k0 + aCol4);
        As[aCol4 + 0][aRow] = av.x;
        As[aCol4 + 1][aRow] = av.y;
        As[aCol4 + 2][aRow] = av.z;
        As[aCol4 + 3][aRow] = av.w;

        float4 bv = make_float4(0.f, 0.f, 0.f, 0.f);
        if (bOk) bv = *reinterpret_cast<const float4*>(Bb + (size_t)(k0 + bRow) * N + bCol4);
        *reinterpret_cast<float4*>(&Bs[bRow][bCol4]) = bv;

        __syncthreads();

        #pragma unroll
        for (int k = 0; k < GBK; k++) {
            float rm[GTM], rn[GTN];
            #pragma unroll
            for (int m = 0; m < GTM; m++) rm[m] = As[k][trow * GTM + m];
            #pragma unroll
            for (int n = 0; n < GTN; n++) rn[n] = Bs[k][tcol * GTN + n];
            #pragma unroll
            for (int m = 0; m < GTM; m++)
                #pragma unroll
                for (int n = 0; n < GTN; n++)
                    acc[m][n] = fmaf(rm[m], rn[n], acc[m][n]);
        }
        __syncthreads();
    }

    #pragma unroll
    for (int m = 0; m < GTM; m++) {
        const int grow = cRow * GBM + trow * GTM + m;
        #pragma unroll
        for (int n = 0; n < GTN; n += 4) {
            const int gcol = cCol * GBN + tcol * GTN + n;
            if (gcol < N) {
                float4 v = make_float4(acc[m][n], acc[m][n + 1], acc[m][n + 2], acc[m][n + 3]);
                *reinterpret_cast<float4*>(C + (size_t)grow * N + gcol) = v;
            }
        }
    }
}

// ---------------- dt / dA precompute ----------------
__global__ void prep_dt(const float* __restrict__ zx,
                        const float* __restrict__ dt_bias,
                        const float* __restrict__ A_log,
                        float* __restrict__ dt_out,
                        float* __restrict__ dA_out)
{
    int idx = blockIdx.x * blockDim.x + threadIdx.x;
    if (idx >= ROWS * NHEADS) return;
    int h = idx & (NHEADS - 1);
    int row = idx >> 5;
    float v = zx[(size_t)row * D_IN_PROJ + (D_IN_PROJ - NHEADS) + h] + dt_bias[h];
    // stable softplus
    float dt = (v > 0.f) ? (v + log1pf(expf(-v))) : log1pf(expf(v));
    float A = -expf(A_log[h]);
    dt_out[idx] = dt;
    dA_out[idx] = expf(dt * A);
}

// ---------------- depthwise causal conv1d + SiLU ----------------
__global__ void conv_silu(const float* __restrict__ zx,
                          const float* __restrict__ conv_w,
                          const float* __restrict__ conv_b,
                          float* __restrict__ out)
{
    size_t idx = (size_t)blockIdx.x * blockDim.x + threadIdx.x;
    if (idx >= (size_t)ROWS * CONV_DIM) return;
    int c   = (int)(idx % CONV_DIM);
    int row = (int)(idx / CONV_DIM);
    int l   = row & (SEQLEN - 1);

    const float* col = zx + (size_t)row * D_IN_PROJ + D_INNER + c;
    float acc = conv_b[c];
    #pragma unroll
    for (int k = 0; k < D_CONV; k++) {
        int dl = l - (D_CONV - 1) + k;
        if (dl >= 0)
            acc = fmaf(conv_w[k * CONV_DIM + c],
                       col[(long)(k - (D_CONV - 1)) * D_IN_PROJ], acc);
    }
    // SiLU
    out[idx] = acc / (1.f + expf(-acc));
}

// ---------------- selective state-space scan ----------------
// One block per (b,h). 128 threads: p = tid&63, n-half = tid>>6 (32 states each).
__global__ __launch_bounds__(128) void ssm_scan(
    const float* __restrict__ conv,   // [ROWS][CONV_DIM]: x | B | C
    const float* __restrict__ dtv,    // [ROWS][NHEADS]
    const float* __restrict__ dAv,    // [ROWS][NHEADS]
    const float* __restrict__ Dparm,  // [NHEADS]
    float* __restrict__ y)            // [ROWS][D_INNER]
{
    const int b = blockIdx.x >> 5;
    const int h = blockIdx.x & 31;
    const int tid = threadIdx.x;
    const int p = tid & 63;
    const int nb = (tid >> 6) * 32;

    __shared__ float sx[2][64], sB[2][64], sC[2][64];
    __shared__ float sdt[2][2];
    __shared__ float sacc[2][128];

    float st[32];
    #pragma unroll
    for (int i = 0; i < 32; i++) st[i] = 0.f;
    const float Dh = Dparm[h];

    // stage loader
    auto stage = [&](int l, int buf) {
        int row = b * SEQLEN + l;
        const float* base = conv + (size_t)row * CONV_DIM;
        if (tid < 64) {
            sx[buf][tid] = base[h * HEADDIM + tid];
            sB[buf][tid] = base[D_INNER + tid];
            sC[buf][tid] = base[D_INNER + D_STATE + tid];
        }
        if (tid == 0) {
            sdt[buf][0] = dtv[(size_t)row * NHEADS + h];
            sdt[buf][1] = dAv[(size_t)row * NHEADS + h];
        }
    };

    stage(0, 0);
    __syncthreads();

    for (int l = 0; l < SEQLEN; l++) {
        const int buf = l & 1;
        if (l + 1 < SEQLEN) stage(l + 1, buf ^ 1);

        const float dt_t = sdt[buf][0];
        const float dA_t = sdt[buf][1];
        const float dtx  = dt_t * sx[buf][p];

        float acc = 0.f;
        #pragma unroll
        for (int i = 0; i < 32; i++) {
            float Bv = sB[buf][nb + i];
            float Cv = sC[buf][nb + i];
            st[i] = fmaf(st[i], dA_t, dtx * Bv);
            acc = fmaf(st[i], Cv, acc);
        }
        sacc[buf][tid] = acc;
        __syncthreads();
        if (tid < 64) {
            float yv = sacc[buf][tid] + sacc[buf][tid + 64] + Dh * sx[buf][tid];
            y[(size_t)(b * SEQLEN + l) * D_INNER + h * HEADDIM + tid] = yv;
        }
        // parity double-buffering on sacc/stage buffers -> one sync per step is safe
    }
}

// ---------------- gate (y * silu(z)) + RMSNorm ----------------
__global__ __launch_bounds__(256) void gate_rmsnorm(
    const float* __restrict__ yraw,
    const float* __restrict__ zx,
    const float* __restrict__ norm_w,
    float* __restrict__ out)
{
    const int row = blockIdx.x;
    const int tid = threadIdx.x;
    const float* yr = yraw + (size_t)row * D_INNER;
    const float* z  = zx + (size_t)row * D_IN_PROJ;   // z = cols [0, D_INNER)

    float v[8];
    float ss = 0.f;
    #pragma unroll
    for (int i = 0; i < 8; i++) {
        int c = tid + i * 256;
        float zz = z[c];
        float g  = zz / (1.f + expf(-zz));
        float t  = yr[c] * g;
        v[i] = t;
        ss = fmaf(t, t, ss);
    }
    // block reduce
    #pragma unroll
    for (int off = 16; off > 0; off >>= 1)
        ss += __shfl_xor_sync(0xffffffffu, ss, off);
    __shared__ float swarp[8];
    __shared__ float stot;
    if ((tid & 31) == 0) swarp[tid >> 5] = ss;
    __syncthreads();
    if (tid == 0) {
        float t = 0.f;
        #pragma unroll
        for (int i = 0; i < 8; i++) t += swarp[i];
        stot = t;
    }
    __syncthreads();
    const float scale = rsqrtf(stot * (1.f / D_INNER) + 1e-5f);
    #pragma unroll
    for (int i = 0; i < 8; i++) {
        int c = tid + i * 256;
        out[(size_t)row * D_INNER + c] = v[i] * scale * norm_w[c];
    }
}

// ---------------- launcher ----------------
extern "C" void kernel_launch(void* const* d_in, const int* in_sizes, int n_in,
                              void* d_out, int out_size)
{
    const float* u       = (const float*)d_in[0];
    const float* W_in    = (const float*)d_in[1];
    const float* conv_w  = (const float*)d_in[2];
    const float* conv_b  = (const float*)d_in[3];
    const float* dt_bias = (const float*)d_in[4];
    const float* A_log   = (const float*)d_in[5];
    const float* Dp      = (const float*)d_in[6];
    const float* norm_w  = (const float*)d_in[7];
    const float* W_out   = (const float*)d_in[8];
    float* out = (float*)d_out;

    float *zx, *cv, *dtp, *dAp, *yp, *ynp;
    cudaGetSymbolAddress((void**)&zx,  g_zx);
    cudaGetSymbolAddress((void**)&cv,  g_conv);
    cudaGetSymbolAddress((void**)&dtp, g_dt);
    cudaGetSymbolAddress((void**)&dAp, g_dA);
    cudaGetSymbolAddress((void**)&yp,  g_y);
    cudaGetSymbolAddress((void**)&ynp, g_yn);

    // 1) zxbcdt = u @ W_in   (8192 x 1024) @ (1024 x 4256)
    {
        dim3 grid((D_IN_PROJ + GBN - 1) / GBN, ROWS / GBM);
        sgemm128<<<grid, 256>>>(u, W_in, zx, ROWS, D_IN_PROJ, D_MODEL);
    }
    // 2) dt / dA precompute
    prep_dt<<<(ROWS * NHEADS + 255) / 256, 256>>>(zx, dt_bias, A_log, dtp, dAp);
    // 3) depthwise conv + silu
    {
        size_t total = (size_t)ROWS * CONV_DIM;
        conv_silu<<<(unsigned)((total + 255) / 256), 256>>>(zx, conv_w, conv_b, cv);
    }
    // 4) selective scan (+ x*D)
    ssm_scan<<<B_SZ * NHEADS, 128>>>(cv, dtp, dAp, Dp, yp);
    // 5) gate + rmsnorm
    gate_rmsnorm<<<ROWS, 256>>>(yp, zx, norm_w, ynp);
    // 6) out = yn @ W_out   (8192 x 2048) @ (2048 x 1024)
    {
        dim3 grid(D_MODEL / GBN, ROWS / GBM);
        sgemm128<<<grid, 256>>>(ynp, W_out, out, ROWS, D_MODEL, D_INNER);
    }
}

// round 3
// speedup vs baseline: 1.5866x; 1.5866x over previous
#include <cuda_runtime.h>
#include <cuda_bf16.h>
#include <cstdint>

// ---------------- problem constants ----------------
#define D_MODEL   1024
#define D_STATE   64
#define D_CONV    4
#define HEADDIM   64
#define D_INNER   2048
#define NHEADS    32
#define CONV_DIM  2176            // D_INNER + 2*D_STATE
#define D_IN_PROJ 4256            // 2*D_INNER + 2*D_STATE + NHEADS
#define B_SZ      4
#define SEQLEN    2048
#define ROWS      (B_SZ * SEQLEN) // 8192
#define NP1       4352            // D_IN_PROJ padded to 128

// ---------------- scratch (static device memory) ----------------
__device__ float g_zx[(size_t)ROWS * D_IN_PROJ];   // u @ W_in (fp32)
__device__ float g_conv[(size_t)ROWS * CONV_DIM];  // conv+silu output
__device__ float g_dt[(size_t)ROWS * NHEADS];
__device__ float g_dA[(size_t)ROWS * NHEADS];
__device__ float g_y[(size_t)ROWS * D_INNER];      // scan output (+ x*D)

__device__ __nv_bfloat16 g_u_hi[(size_t)ROWS * D_MODEL];
__device__ __nv_bfloat16 g_u_lo[(size_t)ROWS * D_MODEL];
__device__ __nv_bfloat16 g_wint_hi[(size_t)NP1 * D_MODEL];      // W_in^T padded [NP1, 1024]
__device__ __nv_bfloat16 g_wint_lo[(size_t)NP1 * D_MODEL];
__device__ __nv_bfloat16 g_woutt_hi[(size_t)D_MODEL * D_INNER]; // W_out^T [1024, 2048]
__device__ __nv_bfloat16 g_woutt_lo[(size_t)D_MODEL * D_INNER];
__device__ __nv_bfloat16 g_yn_hi[(size_t)ROWS * D_INNER];
__device__ __nv_bfloat16 g_yn_lo[(size_t)ROWS * D_INNER];

// ================= low-level helpers (arch-neutral PTX: sm_80+) =================
__device__ __forceinline__ uint32_t smem_u32(const void* p) {
    uint32_t a;
    asm("{ .reg .u64 t; cvta.to.shared.u64 t, %1; cvt.u32.u64 %0, t; }" : "=r"(a) : "l"(p));
    return a;
}
__device__ __forceinline__ void cp_async16(uint32_t sdst, const void* gsrc) {
    asm volatile("cp.async.cg.shared.global [%0], [%1], 16;" :: "r"(sdst), "l"(gsrc));
}
__device__ __forceinline__ void cp_commit() {
    asm volatile("cp.async.commit_group;" ::: "memory");
}
__device__ __forceinline__ void cp_wait1() {
    asm volatile("cp.async.wait_group 1;" ::: "memory");
}
__device__ __forceinline__ void ldsm_x4(uint32_t& r0, uint32_t& r1, uint32_t& r2, uint32_t& r3,
                                        uint32_t addr) {
    asm volatile("ldmatrix.sync.aligned.m8n8.x4.shared.b16 {%0,%1,%2,%3}, [%4];"
                 : "=r"(r0), "=r"(r1), "=r"(r2), "=r"(r3) : "r"(addr));
}
__device__ __forceinline__ void mma16816(float& d0, float& d1, float& d2, float& d3,
                                         uint32_t a0, uint32_t a1, uint32_t a2, uint32_t a3,
                                         uint32_t b0, uint32_t b1) {
    asm volatile(
        "mma.sync.aligned.m16n8k16.row.col.f32.bf16.bf16.f32 "
        "{%0,%1,%2,%3}, {%4,%5,%6,%7}, {%8,%9}, {%0,%1,%2,%3};"
        : "+f"(d0), "+f"(d1), "+f"(d2), "+f"(d3)
        : "r"(a0), "r"(a1), "r"(a2), "r"(a3), "r"(b0), "r"(b1));
}

// ================= split-bf16 HMMA GEMM =================
// C[M, Nout] (fp32, row stride ldc) = (Ahi+Alo)[M,K] @ (Bhi+Blo)^T, B stored [NPAD][K].
// 128x128 CTA tile, BK=32, 8 warps (2x4), 2-stage cp.async pipeline.
#define LDSB   80                       // smem row stride in bytes (32 bf16 + pad)
#define TILE_B (128 * LDSB)             // 10240 B per operand tile
#define STAGE_B (4 * TILE_B)            // 40960 B per stage (Ahi,Alo,Bhi,Blo)
#define GEMM_SMEM (2 * STAGE_B)         // 81920 B

__global__ __launch_bounds__(256, 1) void gemm_mma(
    const __nv_bfloat16* __restrict__ Ahi, const __nv_bfloat16* __restrict__ Alo,
    const __nv_bfloat16* __restrict__ Bhi, const __nv_bfloat16* __restrict__ Blo,
    float* __restrict__ C, int K, int Nout, int ldc)
{
    extern __shared__ __align__(16) char smem[];
    const uint32_t sbase = smem_u32(smem);

    const int tid  = threadIdx.x;
    const int lane = tid & 31;
    const int wid  = tid >> 5;
    const int wm   = wid & 1;      // 0..1 -> 64-row block
    const int wn   = wid >> 1;     // 0..3 -> 32-col block
    const int Mbase = blockIdx.y * 128;
    const int Nbase = blockIdx.x * 128;

    const __nv_bfloat16* srcs[4];
    srcs[0] = Ahi + (size_t)Mbase * K;
    srcs[1] = Alo + (size_t)Mbase * K;
    srcs[2] = Bhi + (size_t)Nbase * K;
    srcs[3] = Blo + (size_t)Nbase * K;

    const int lr = tid >> 2;       // 0..63 (row pair base)
    const int lc = tid & 3;        // 0..3  (16B chunk)

    // issue one k-tile (32 bf16 wide) into stage s
    auto issue = [&](int kt, int s) {
        const uint32_t sb = sbase + (uint32_t)s * STAGE_B;
        #pragma unroll
        for (int op = 0; op < 4; op++) {
            const __nv_bfloat16* src = srcs[op] + (size_t)kt * 32 + lc * 8;
            const uint32_t dst = sb + (uint32_t)op * TILE_B + lc * 16;
            #pragma unroll
            for (int h = 0; h < 2; h++) {
                int r = lr + h * 64;
                cp_async16(dst + (uint32_t)r * LDSB, src + (size_t)r * K);
            }
        }
    };

    float acc[4][4][4];
    #pragma unroll
    for (int m = 0; m < 4; m++)
        #pragma unroll
        for (int n = 0; n < 4; n++)
            #pragma unroll
            for (int e = 0; e < 4; e++) acc[m][n][e] = 0.f;

    const int KT = K / 32;
    issue(0, 0); cp_commit();
    issue(1, 1); cp_commit();

    // per-lane ldmatrix address components
    const int a_row = (lane & 15);            // + m0
    const int a_k16 = (lane >> 4) * 16;       // bytes (+8 elems for upper half)
    const int b_row = (lane & 7) + ((lane >> 4) & 1) * 8;   // + n0
    const int b_k16 = ((lane >> 3) & 1) * 16;               // bytes

    for (int kt = 0; kt < KT; kt++) {
        cp_wait1();
        __syncthreads();
        const uint32_t sb = sbase + (uint32_t)(kt & 1) * STAGE_B;
        const uint32_t sAhi = sb;
        const uint32_t sAlo = sb + TILE_B;
        const uint32_t sBhi = sb + 2 * TILE_B;
        const uint32_t sBlo = sb + 3 * TILE_B;

        #pragma unroll
        for (int ks = 0; ks < 2; ks++) {
            const uint32_t koff = (uint32_t)ks * 32;  // 16 bf16 = 32 bytes

            uint32_t ah[4][4], al[4][4];
            #pragma unroll
            for (int mt = 0; mt < 4; mt++) {
                const uint32_t rowoff = (uint32_t)(wm * 64 + mt * 16 + a_row) * LDSB + koff + a_k16;
                ldsm_x4(ah[mt][0], ah[mt][1], ah[mt][2], ah[mt][3], sAhi + rowoff);
                ldsm_x4(al[mt][0], al[mt][1], al[mt][2], al[mt][3], sAlo + rowoff);
            }
            uint32_t bh[4][2], bl[4][2];
            #pragma unroll
            for (int np = 0; np < 2; np++) {   // each x4 covers two n8 tiles
                const uint32_t rowoff = (uint32_t)(wn * 32 + np * 16 + b_row) * LDSB + koff + b_k16;
                ldsm_x4(bh[np*2][0], bh[np*2][1], bh[np*2+1][0], bh[np*2+1][1], sBhi + rowoff);
                ldsm_x4(bl[np*2][0], bl[np*2][1], bl[np*2+1][0], bl[np*2+1][1], sBlo + rowoff);
            }
            #pragma unroll
            for (int mt = 0; mt < 4; mt++)
                #pragma unroll
                for (int nt = 0; nt < 4; nt++) {
                    float* d = acc[mt][nt];
                    mma16816(d[0], d[1], d[2], d[3],
                             ah[mt][0], ah[mt][1], ah[mt][2], ah[mt][3], bh[nt][0], bh[nt][1]);
                    mma16816(d[0], d[1], d[2], d[3],
                             ah[mt][0], ah[mt][1], ah[mt][2], ah[mt][3], bl[nt][0], bl[nt][1]);
                    mma16816(d[0], d[1], d[2], d[3],
                             al[mt][0], al[mt][1], al[mt][2], al[mt][3], bh[nt][0], bh[nt][1]);
                }
        }
        __syncthreads();
        if (kt + 2 < KT) issue(kt + 2, kt & 1);
        cp_commit();
    }

    // epilogue
    #pragma unroll
    for (int mt = 0; mt < 4; mt++) {
        const int row0 = Mbase + wm * 64 + mt * 16 + (lane >> 2);
        #pragma unroll
        for (int nt = 0; nt < 4; nt++) {
            const int col = Nbase + wn * 32 + nt * 8 + (lane & 3) * 2;
            if (col < Nout) {
                float2 v0 = make_float2(acc[mt][nt][0], acc[mt][nt][1]);
                float2 v1 = make_float2(acc[mt][nt][2], acc[mt][nt][3]);
                *reinterpret_cast<float2*>(C + (size_t)row0 * ldc + col) = v0;
                *reinterpret_cast<float2*>(C + (size_t)(row0 + 8) * ldc + col) = v1;
            }
        }
    }
}

// ================= conversions =================
__global__ void convert_split(const float4* __restrict__ in,
                              __nv_bfloat16* __restrict__ hi,
                              __nv_bfloat16* __restrict__ lo, int n4)
{
    int i = blockIdx.x * blockDim.x + threadIdx.x;
    if (i >= n4) return;
    float4 v = in[i];
    __nv_bfloat16 h[4], l[4];
    float f[4] = {v.x, v.y, v.z, v.w};
    #pragma unroll
    for (int j = 0; j < 4; j++) {
        h[j] = __float2bfloat16(f[j]);
        l[j] = __float2bfloat16(f[j] - __bfloat162float(h[j]));
    }
    *reinterpret_cast<uint2*>(hi + (size_t)i * 4) = *reinterpret_cast<uint2*>(h);
    *reinterpret_cast<uint2*>(lo + (size_t)i * 4) = *reinterpret_cast<uint2*>(l);
}

// W[K,N] fp32 -> T[NP,K] bf16 hi/lo (transpose + split; rows n>=N zero-filled)
__global__ __launch_bounds__(256) void transpose_split(
    const float* __restrict__ W, int K, int N,
    __nv_bfloat16* __restrict__ Thi, __nv_bfloat16* __restrict__ Tlo)
{
    __shared__ float t[32][33];
    const int n0 = blockIdx.x * 32, k0 = blockIdx.y * 32;
    const int tx = threadIdx.x & 31, ty = threadIdx.x >> 5;
    #pragma unroll
    for (int j = 0; j < 4; j++) {
        int k = k0 + ty + j * 8;
        int n = n0 + tx;
        t[ty + j * 8][tx] = (n < N) ? W[(size_t)k * N + n] : 0.f;
    }
    __syncthreads();
    #pragma unroll
    for (int j = 0; j < 4; j++) {
        int n = n0 + ty + j * 8;   // output row
        int k = k0 + tx;
        float v = t[tx][ty + j * 8];
        __nv_bfloat16 h = __float2bfloat16(v);
        Thi[(size_t)n * K + k] = h;
        Tlo[(size_t)n * K + k] = __float2bfloat16(v - __bfloat162float(h));
    }
}

// ---------------- dt / dA precompute ----------------
__global__ void prep_dt(const float* __restrict__ zx,
                        const float* __restrict__ dt_bias,
                        const float* __restrict__ A_log,
                        float* __restrict__ dt_out,
                        float* __restrict__ dA_out)
{
    int idx = blockIdx.x * blockDim.x + threadIdx.x;
    if (idx >= ROWS * NHEADS) return;
    int h = idx & (NHEADS - 1);
    int row = idx >> 5;
    float v = zx[(size_t)row * D_IN_PROJ + (D_IN_PROJ - NHEADS) + h] + dt_bias[h];
    float dt = (v > 0.f) ? (v + log1pf(expf(-v))) : log1pf(expf(v));
    float A = -expf(A_log[h]);
    dt_out[idx] = dt;
    dA_out[idx] = expf(dt * A);
}

// ---------------- depthwise causal conv1d + SiLU ----------------
__global__ void conv_silu(const float* __restrict__ zx,
                          const float* __restrict__ conv_w,
                          const float* __restrict__ conv_b,
                          float* __restrict__ out)
{
    size_t idx = (size_t)blockIdx.x * blockDim.x + threadIdx.x;
    if (idx >= (size_t)ROWS * CONV_DIM) return;
    int c   = (int)(idx % CONV_DIM);
    int row = (int)(idx / CONV_DIM);
    int l   = row & (SEQLEN - 1);

    const float* col = zx + (size_t)row * D_IN_PROJ + D_INNER + c;
    float acc = conv_b[c];
    #pragma unroll
    for (int k = 0; k < D_CONV; k++) {
        int dl = l - (D_CONV - 1) + k;
        if (dl >= 0)
            acc = fmaf(conv_w[k * CONV_DIM + c],
                       col[(long)(k - (D_CONV - 1)) * D_IN_PROJ], acc);
    }
    out[idx] = acc / (1.f + expf(-acc));
}

// ---------------- selective state-space scan (R1 known-good) ----------------
__global__ __launch_bounds__(128) void ssm_scan(
    const float* __restrict__ conv,   // [ROWS][CONV_DIM]: x | B | C
    const float* __restrict__ dtv,    // [ROWS][NHEADS]
    const float* __restrict__ dAv,    // [ROWS][NHEADS]
    const float* __restrict__ Dparm,  // [NHEADS]
    float* __restrict__ y)            // [ROWS][D_INNER]
{
    const int b = blockIdx.x >> 5;
    const int h = blockIdx.x & 31;
    const int tid = threadIdx.x;
    const int p = tid & 63;
    const int nb = (tid >> 6) * 32;

    __shared__ float sx[2][64], sB[2][64], sC[2][64];
    __shared__ float sdt[2][2];
    __shared__ float sacc[2][128];

    float st[32];
    #pragma unroll
    for (int i = 0; i < 32; i++) st[i] = 0.f;
    const float Dh = Dparm[h];

    auto stage = [&](int l, int buf) {
        int row = b * SEQLEN + l;
        const float* base = conv + (size_t)row * CONV_DIM;
        if (tid < 64) {
            sx[buf][tid] = base[h * HEADDIM + tid];
            sB[buf][tid] = base[D_INNER + tid];
            sC[buf][tid] = base[D_INNER + D_STATE + tid];
        }
        if (tid == 0) {
            sdt[buf][0] = dtv[(size_t)row * NHEADS + h];
            sdt[buf][1] = dAv[(size_t)row * NHEADS + h];
        }
    };

    stage(0, 0);
    __syncthreads();

    for (int l = 0; l < SEQLEN; l++) {
        const int buf = l & 1;
        if (l + 1 < SEQLEN) stage(l + 1, buf ^ 1);

        const float dt_t = sdt[buf][0];
        const float dA_t = sdt[buf][1];
        const float dtx  = dt_t * sx[buf][p];

        float acc = 0.f;
        #pragma unroll
        for (int i = 0; i < 32; i++) {
            float Bv = sB[buf][nb + i];
            float Cv = sC[buf][nb + i];
            st[i] = fmaf(st[i], dA_t, dtx * Bv);
            acc = fmaf(st[i], Cv, acc);
        }
        sacc[buf][tid] = acc;
        __syncthreads();
        if (tid < 64) {
            float yv = sacc[buf][tid] + sacc[buf][tid + 64] + Dh * sx[buf][tid];
            y[(size_t)(b * SEQLEN + l) * D_INNER + h * HEADDIM + tid] = yv;
        }
    }
}

// ---------------- gate (y * silu(z)) + RMSNorm -> bf16 hi/lo ----------------
__global__ __launch_bounds__(256) void gate_rmsnorm(
    const float* __restrict__ yraw,
    const float* __restrict__ zx,
    const float* __restrict__ norm_w,
    __nv_bfloat16* __restrict__ out_hi,
    __nv_bfloat16* __restrict__ out_lo)
{
    const int row = blockIdx.x;
    const int tid = threadIdx.x;
    const float* yr = yraw + (size_t)row * D_INNER;
    const float* z  = zx + (size_t)row * D_IN_PROJ;

    float v[8];
    float ss = 0.f;
    #pragma unroll
    for (int i = 0; i < 8; i++) {
        int c = tid + i * 256;
        float zz = z[c];
        float g  = zz / (1.f + expf(-zz));
        float t  = yr[c] * g;
        v[i] = t;
        ss = fmaf(t, t, ss);
    }
    #pragma unroll
    for (int off = 16; off > 0; off >>= 1)
        ss += __shfl_xor_sync(0xffffffffu, ss, off);
    __shared__ float swarp[8];
    __shared__ float stot;
    if ((tid & 31) == 0) swarp[tid >> 5] = ss;
    __syncthreads();
    if (tid == 0) {
        float t = 0.f;
        #pragma unroll
        for (int i = 0; i < 8; i++) t += swarp[i];
        stot = t;
    }
    __syncthreads();
    const float scale = rsqrtf(stot * (1.f / D_INNER) + 1e-5f);
    #pragma unroll
    for (int i = 0; i < 8; i++) {
        int c = tid + i * 256;
        float t = v[i] * scale * norm_w[c];
        __nv_bfloat16 h = __float2bfloat16(t);
        out_hi[(size_t)row * D_INNER + c] = h;
        out_lo[(size_t)row * D_INNER + c] = __float2bfloat16(t - __bfloat162float(h));
    }
}

// ---------------- launcher ----------------
extern "C" void kernel_launch(void* const* d_in, const int* in_sizes, int n_in,
                              void* d_out, int out_size)
{
    const float* u       = (const float*)d_in[0];
    const float* W_in    = (const float*)d_in[1];
    const float* conv_w  = (const float*)d_in[2];
    const float* conv_b  = (const float*)d_in[3];
    const float* dt_bias = (const float*)d_in[4];
    const float* A_log   = (const float*)d_in[5];
    const float* Dp      = (const float*)d_in[6];
    const float* norm_w  = (const float*)d_in[7];
    const float* W_out   = (const float*)d_in[8];
    float* out = (float*)d_out;

    float *zx, *cv, *dtp, *dAp, *yp;
    __nv_bfloat16 *uhi, *ulo, *wih, *wil, *woh, *wol, *ynh, *ynl;
    cudaGetSymbolAddress((void**)&zx,  g_zx);
    cudaGetSymbolAddress((void**)&cv,  g_conv);
    cudaGetSymbolAddress((void**)&dtp, g_dt);
    cudaGetSymbolAddress((void**)&dAp, g_dA);
    cudaGetSymbolAddress((void**)&yp,  g_y);
    cudaGetSymbolAddress((void**)&uhi, g_u_hi);
    cudaGetSymbolAddress((void**)&ulo, g_u_lo);
    cudaGetSymbolAddress((void**)&wih, g_wint_hi);
    cudaGetSymbolAddress((void**)&wil, g_wint_lo);
    cudaGetSymbolAddress((void**)&woh, g_woutt_hi);
    cudaGetSymbolAddress((void**)&wol, g_woutt_lo);
    cudaGetSymbolAddress((void**)&ynh, g_yn_hi);
    cudaGetSymbolAddress((void**)&ynl, g_yn_lo);

    cudaFuncSetAttribute(gemm_mma, cudaFuncAttributeMaxDynamicSharedMemorySize, GEMM_SMEM);

    // operand prep
    {
        int n4 = ROWS * D_MODEL / 4;
        convert_split<<<(n4 + 255) / 256, 256>>>((const float4*)u, uhi, ulo, n4);
    }
    transpose_split<<<dim3(NP1 / 32, D_MODEL / 32), 256>>>(W_in, D_MODEL, D_IN_PROJ, wih, wil);
    transpose_split<<<dim3(D_MODEL / 32, D_INNER / 32), 256>>>(W_out, D_INNER, D_MODEL, woh, wol);

    // 1) zxbcdt = u @ W_in
    gemm_mma<<<dim3(NP1 / 128, ROWS / 128), 256, GEMM_SMEM>>>(
        uhi, ulo, wih, wil, zx, D_MODEL, D_IN_PROJ, D_IN_PROJ);

    // 2) dt / dA
    prep_dt<<<(ROWS * NHEADS + 255) / 256, 256>>>(zx, dt_bias, A_log, dtp, dAp);
    // 3) depthwise conv + silu
    {
        size_t total = (size_t)ROWS * CONV_DIM;
        conv_silu<<<(unsigned)((total + 255) / 256), 256>>>(zx, conv_w, conv_b, cv);
    }
    // 4) selective scan (+ x*D)
    ssm_scan<<<B_SZ * NHEADS, 128>>>(cv, dtp, dAp, Dp, yp);
    // 5) gate + rmsnorm -> bf16 hi/lo
    gate_rmsnorm<<<ROWS, 256>>>(yp, zx, norm_w, ynh, ynl);
    // 6) out = yn @ W_out
    gemm_mma<<<dim3(D_MODEL / 128, ROWS / 128), 256, GEMM_SMEM>>>(
        ynh, ynl, woh, wol, out, D_INNER, D_MODEL, D_MODEL);
}

// round 5
// speedup vs baseline: 2.7761x; 1.7497x over previous
#include <cuda_runtime.h>
#include <cuda_bf16.h>
#include <cstdint>

// ---------------- problem constants ----------------
#define D_MODEL   1024
#define D_STATE   64
#define D_CONV    4
#define HEADDIM   64
#define D_INNER   2048
#define NHEADS    32
#define CONV_DIM  2176            // D_INNER + 2*D_STATE
#define D_IN_PROJ 4256            // 2*D_INNER + 2*D_STATE + NHEADS
#define B_SZ      4
#define SEQLEN    2048
#define ROWS      (B_SZ * SEQLEN) // 8192
#define NP1       4352            // D_IN_PROJ padded to 128

// ---------------- scratch (static device memory) ----------------
__device__ float g_zx[(size_t)ROWS * D_IN_PROJ];   // u @ W_in (fp32)
__device__ float g_conv[(size_t)ROWS * CONV_DIM];  // conv+silu output
__device__ float g_dt[(size_t)ROWS * NHEADS];
__device__ float g_dA[(size_t)ROWS * NHEADS];
__device__ float g_y[(size_t)ROWS * D_INNER];      // scan output (+ x*D)

__device__ __nv_bfloat16 g_u_hi[(size_t)ROWS * D_MODEL];
__device__ __nv_bfloat16 g_u_lo[(size_t)ROWS * D_MODEL];
__device__ __nv_bfloat16 g_wint_hi[(size_t)NP1 * D_MODEL];      // W_in^T padded [NP1, 1024]
__device__ __nv_bfloat16 g_wint_lo[(size_t)NP1 * D_MODEL];
__device__ __nv_bfloat16 g_woutt_hi[(size_t)D_MODEL * D_INNER]; // W_out^T [1024, 2048]
__device__ __nv_bfloat16 g_woutt_lo[(size_t)D_MODEL * D_INNER];
__device__ __nv_bfloat16 g_yn_hi[(size_t)ROWS * D_INNER];
__device__ __nv_bfloat16 g_yn_lo[(size_t)ROWS * D_INNER];

// ================= low-level helpers (arch-neutral PTX: sm_80+) =================
__device__ __forceinline__ uint32_t smem_u32(const void* p) {
    uint32_t a;
    asm("{ .reg .u64 t; cvta.to.shared.u64 t, %1; cvt.u32.u64 %0, t; }" : "=r"(a) : "l"(p));
    return a;
}
__device__ __forceinline__ void cp_async16(uint32_t sdst, const void* gsrc) {
    asm volatile("cp.async.cg.shared.global [%0], [%1], 16;" :: "r"(sdst), "l"(gsrc));
}
__device__ __forceinline__ void cp_commit() {
    asm volatile("cp.async.commit_group;" ::: "memory");
}
__device__ __forceinline__ void cp_wait2() {
    asm volatile("cp.async.wait_group 2;" ::: "memory");
}
__device__ __forceinline__ void ldsm_x4(uint32_t& r0, uint32_t& r1, uint32_t& r2, uint32_t& r3,
                                        uint32_t addr) {
    asm volatile("ldmatrix.sync.aligned.m8n8.x4.shared.b16 {%0,%1,%2,%3}, [%4];"
                 : "=r"(r0), "=r"(r1), "=r"(r2), "=r"(r3) : "r"(addr));
}
__device__ __forceinline__ void mma16816(float& d0, float& d1, float& d2, float& d3,
                                         uint32_t a0, uint32_t a1, uint32_t a2, uint32_t a3,
                                         uint32_t b0, uint32_t b1) {
    asm volatile(
        "mma.sync.aligned.m16n8k16.row.col.f32.bf16.bf16.f32 "
        "{%0,%1,%2,%3}, {%4,%5,%6,%7}, {%8,%9}, {%0,%1,%2,%3};"
        : "+f"(d0), "+f"(d1), "+f"(d2), "+f"(d3)
        : "r"(a0), "r"(a1), "r"(a2), "r"(a3), "r"(b0), "r"(b1));
}

// ================= split-bf16 HMMA GEMM (3-stage pipeline) =================
#define LDSB   80                       // smem row stride in bytes (32 bf16 + pad)
#define TILE_B (128 * LDSB)             // 10240 B per operand tile
#define STAGE_B (4 * TILE_B)            // 40960 B per stage (Ahi,Alo,Bhi,Blo)
#define NSTAGE 3
#define GEMM_SMEM (NSTAGE * STAGE_B)    // 122880 B

__global__ __launch_bounds__(256, 1) void gemm_mma(
    const __nv_bfloat16* __restrict__ Ahi, const __nv_bfloat16* __restrict__ Alo,
    const __nv_bfloat16* __restrict__ Bhi, const __nv_bfloat16* __restrict__ Blo,
    float* __restrict__ C, int K, int Nout, int ldc)
{
    extern __shared__ __align__(16) char smem[];
    const uint32_t sbase = smem_u32(smem);

    const int tid  = threadIdx.x;
    const int lane = tid & 31;
    const int wid  = tid >> 5;
    const int wm   = wid & 1;      // 0..1 -> 64-row block
    const int wn   = wid >> 1;     // 0..3 -> 32-col block
    const int Mbase = blockIdx.y * 128;
    const int Nbase = blockIdx.x * 128;

    const __nv_bfloat16* srcs[4];
    srcs[0] = Ahi + (size_t)Mbase * K;
    srcs[1] = Alo + (size_t)Mbase * K;
    srcs[2] = Bhi + (size_t)Nbase * K;
    srcs[3] = Blo + (size_t)Nbase * K;

    const int lr = tid >> 2;       // 0..63 (row pair base)
    const int lc = tid & 3;        // 0..3  (16B chunk)

    auto issue = [&](int kt, int s) {
        const uint32_t sb = sbase + (uint32_t)s * STAGE_B;
        #pragma unroll
        for (int op = 0; op < 4; op++) {
            const __nv_bfloat16* src = srcs[op] + (size_t)kt * 32 + lc * 8;
            const uint32_t dst = sb + (uint32_t)op * TILE_B + lc * 16;
            #pragma unroll
            for (int h = 0; h < 2; h++) {
                int r = lr + h * 64;
                cp_async16(dst + (uint32_t)r * LDSB, src + (size_t)r * K);
            }
        }
    };

    float acc[4][4][4];
    #pragma unroll
    for (int m = 0; m < 4; m++)
        #pragma unroll
        for (int n = 0; n < 4; n++)
            #pragma unroll
            for (int e = 0; e < 4; e++) acc[m][n][e] = 0.f;

    const int KT = K / 32;
    issue(0, 0); cp_commit();
    issue(1, 1); cp_commit();
    issue(2, 2); cp_commit();

    const int a_row = (lane & 15);
    const int a_k16 = (lane >> 4) * 16;
    const int b_row = (lane & 7) + ((lane >> 4) & 1) * 8;
    const int b_k16 = ((lane >> 3) & 1) * 16;

    int stage = 0;
    for (int kt = 0; kt < KT; kt++) {
        cp_wait2();
        __syncthreads();
        const uint32_t sb = sbase + (uint32_t)stage * STAGE_B;
        const uint32_t sAhi = sb;
        const uint32_t sAlo = sb + TILE_B;
        const uint32_t sBhi = sb + 2 * TILE_B;
        const uint32_t sBlo = sb + 3 * TILE_B;

        #pragma unroll
        for (int ks = 0; ks < 2; ks++) {
            const uint32_t koff = (uint32_t)ks * 32;

            uint32_t ah[4][4], al[4][4];
            #pragma unroll
            for (int mt = 0; mt < 4; mt++) {
                const uint32_t rowoff = (uint32_t)(wm * 64 + mt * 16 + a_row) * LDSB + koff + a_k16;
                ldsm_x4(ah[mt][0], ah[mt][1], ah[mt][2], ah[mt][3], sAhi + rowoff);
                ldsm_x4(al[mt][0], al[mt][1], al[mt][2], al[mt][3], sAlo + rowoff);
            }
            uint32_t bh[4][2], bl[4][2];
            #pragma unroll
            for (int np = 0; np < 2; np++) {
                const uint32_t rowoff = (uint32_t)(wn * 32 + np * 16 + b_row) * LDSB + koff + b_k16;
                ldsm_x4(bh[np*2][0], bh[np*2][1], bh[np*2+1][0], bh[np*2+1][1], sBhi + rowoff);
                ldsm_x4(bl[np*2][0], bl[np*2][1], bl[np*2+1][0], bl[np*2+1][1], sBlo + rowoff);
            }
            #pragma unroll
            for (int mt = 0; mt < 4; mt++)
                #pragma unroll
                for (int nt = 0; nt < 4; nt++) {
                    float* d = acc[mt][nt];
                    mma16816(d[0], d[1], d[2], d[3],
                             ah[mt][0], ah[mt][1], ah[mt][2], ah[mt][3], bh[nt][0], bh[nt][1]);
                    mma16816(d[0], d[1], d[2], d[3],
                             ah[mt][0], ah[mt][1], ah[mt][2], ah[mt][3], bl[nt][0], bl[nt][1]);
                    mma16816(d[0], d[1], d[2], d[3],
                             al[mt][0], al[mt][1], al[mt][2], al[mt][3], bh[nt][0], bh[nt][1]);
                }
        }
        __syncthreads();
        if (kt + 3 < KT) issue(kt + 3, stage);
        cp_commit();
        stage = (stage == NSTAGE - 1) ? 0 : stage + 1;
    }

    #pragma unroll
    for (int mt = 0; mt < 4; mt++) {
        const int row0 = Mbase + wm * 64 + mt * 16 + (lane >> 2);
        #pragma unroll
        for (int nt = 0; nt < 4; nt++) {
            const int col = Nbase + wn * 32 + nt * 8 + (lane & 3) * 2;
            if (col < Nout) {
                float2 v0 = make_float2(acc[mt][nt][0], acc[mt][nt][1]);
                float2 v1 = make_float2(acc[mt][nt][2], acc[mt][nt][3]);
                *reinterpret_cast<float2*>(C + (size_t)row0 * ldc + col) = v0;
                *reinterpret_cast<float2*>(C + (size_t)(row0 + 8) * ldc + col) = v1;
            }
        }
    }
}

// ================= conversions =================
__global__ void convert_split(const float4* __restrict__ in,
                              __nv_bfloat16* __restrict__ hi,
                              __nv_bfloat16* __restrict__ lo, int n4)
{
    int i = blockIdx.x * blockDim.x + threadIdx.x;
    if (i >= n4) return;
    float4 v = in[i];
    __nv_bfloat16 h[4], l[4];
    float f[4] = {v.x, v.y, v.z, v.w};
    #pragma unroll
    for (int j = 0; j < 4; j++) {
        h[j] = __float2bfloat16(f[j]);
        l[j] = __float2bfloat16(f[j] - __bfloat162float(h[j]));
    }
    *reinterpret_cast<uint2*>(hi + (size_t)i * 4) = *reinterpret_cast<uint2*>(h);
    *reinterpret_cast<uint2*>(lo + (size_t)i * 4) = *reinterpret_cast<uint2*>(l);
}

__global__ __launch_bounds__(256) void transpose_split(
    const float* __restrict__ W, int K, int N,
    __nv_bfloat16* __restrict__ Thi, __nv_bfloat16* __restrict__ Tlo)
{
    __shared__ float t[32][33];
    const int n0 = blockIdx.x * 32, k0 = blockIdx.y * 32;
    const int tx = threadIdx.x & 31, ty = threadIdx.x >> 5;
    #pragma unroll
    for (int j = 0; j < 4; j++) {
        int k = k0 + ty + j * 8;
        int n = n0 + tx;
        t[ty + j * 8][tx] = (n < N) ? W[(size_t)k * N + n] : 0.f;
    }
    __syncthreads();
    #pragma unroll
    for (int j = 0; j < 4; j++) {
        int n = n0 + ty + j * 8;
        int k = k0 + tx;
        float v = t[tx][ty + j * 8];
        __nv_bfloat16 h = __float2bfloat16(v);
        Thi[(size_t)n * K + k] = h;
        Tlo[(size_t)n * K + k] = __float2bfloat16(v - __bfloat162float(h));
    }
}

// ---------------- dt / dA precompute ----------------
__global__ void prep_dt(const float* __restrict__ zx,
                        const float* __restrict__ dt_bias,
                        const float* __restrict__ A_log,
                        float* __restrict__ dt_out,
                        float* __restrict__ dA_out)
{
    int idx = blockIdx.x * blockDim.x + threadIdx.x;
    if (idx >= ROWS * NHEADS) return;
    int h = idx & (NHEADS - 1);
    int row = idx >> 5;
    float v = zx[(size_t)row * D_IN_PROJ + (D_IN_PROJ - NHEADS) + h] + dt_bias[h];
    float dt = (v > 0.f) ? (v + log1pf(expf(-v))) : log1pf(expf(v));
    float A = -expf(A_log[h]);
    dt_out[idx] = dt;
    dA_out[idx] = expf(dt * A);
}

// ---------------- depthwise causal conv1d + SiLU (coalesced float4) ----------------
__global__ __launch_bounds__(256) void conv_silu2(
    const float* __restrict__ zx,
    const float* __restrict__ conv_w,
    const float* __restrict__ conv_b,
    float* __restrict__ out)
{
    const int row = blockIdx.x;
    const int l   = row & (SEQLEN - 1);
    const float* base = zx + (size_t)row * D_IN_PROJ + D_INNER;
    float* orow = out + (size_t)row * CONV_DIM;

    for (int c4 = threadIdx.x; c4 < CONV_DIM / 4; c4 += 256) {
        const int c = c4 * 4;
        float4 acc = *reinterpret_cast<const float4*>(conv_b + c);
        #pragma unroll
        for (int k = 0; k < D_CONV; k++) {
            int dl = l - (D_CONV - 1) + k;
            if (dl >= 0) {
                float4 w = *reinterpret_cast<const float4*>(conv_w + k * CONV_DIM + c);
                float4 v = *reinterpret_cast<const float4*>(
                    base + (long)(k - (D_CONV - 1)) * D_IN_PROJ + c);
                acc.x = fmaf(w.x, v.x, acc.x);
                acc.y = fmaf(w.y, v.y, acc.y);
                acc.z = fmaf(w.z, v.z, acc.z);
                acc.w = fmaf(w.w, v.w, acc.w);
            }
        }
        acc.x = acc.x / (1.f + expf(-acc.x));
        acc.y = acc.y / (1.f + expf(-acc.y));
        acc.z = acc.z / (1.f + expf(-acc.z));
        acc.w = acc.w / (1.f + expf(-acc.w));
        *reinterpret_cast<float4*>(orow + c) = acc;
    }
}

// ---------------- selective scan: 256 threads, chunked, sync-free inner loop ----------------
#define CH 8
__global__ __launch_bounds__(256) void ssm_scan3(
    const float* __restrict__ conv, const float* __restrict__ dtv,
    const float* __restrict__ dAv, const float* __restrict__ Dparm,
    float* __restrict__ y)
{
    const int b = blockIdx.x >> 5;
    const int h = blockIdx.x & 31;
    const int tid = threadIdx.x;
    const int p = tid & 63;
    const int g = tid >> 6;           // 0..3, states [g*16, g*16+16)
    const int nb = g * 16;

    __shared__ __align__(16) float sx[2][CH][64];
    __shared__ __align__(16) float sB[2][CH][64];
    __shared__ __align__(16) float sC[2][CH][64];
    __shared__ float sdt[2][CH], sdA[2][CH];
    __shared__ __align__(16) float sacc[CH][256];

    float st[16];
    #pragma unroll
    for (int i = 0; i < 16; i++) st[i] = 0.f;
    const float Dh = Dparm[h];
    const size_t rowbase = (size_t)b * SEQLEN;

    // slot -> (l8, array, quad). 384 slots per chunk: tid (all), tid+256 (tid<128).
    auto g_ptr = [&](int slot, int chunk) -> const float* {
        int l8 = slot / 48; int rem = slot % 48; int a = rem >> 4; int q = rem & 15;
        size_t row = rowbase + (size_t)chunk * CH + l8;
        int off = (a == 0) ? h * HEADDIM : (a == 1) ? D_INNER : (D_INNER + D_STATE);
        return conv + row * CONV_DIM + off + q * 4;
    };
    auto s_ptr = [&](int slot, int buf) -> float* {
        int l8 = slot / 48; int rem = slot % 48; int a = rem >> 4; int q = rem & 15;
        float* base = (a == 0) ? &sx[buf][l8][0] : (a == 1) ? &sB[buf][l8][0] : &sC[buf][l8][0];
        return base + q * 4;
    };

    // preload chunk 0
    {
        float4 v0 = *reinterpret_cast<const float4*>(g_ptr(tid, 0));
        *reinterpret_cast<float4*>(s_ptr(tid, 0)) = v0;
        if (tid < 128) {
            float4 v1 = *reinterpret_cast<const float4*>(g_ptr(tid + 256, 0));
            *reinterpret_cast<float4*>(s_ptr(tid + 256, 0)) = v1;
        }
        if (tid < 16) {
            int l8 = tid >> 1;
            size_t row = rowbase + l8;
            if (tid & 1) sdA[0][l8] = dAv[row * NHEADS + h];
            else         sdt[0][l8] = dtv[row * NHEADS + h];
        }
        __syncthreads();
    }

    const int NCHUNK = SEQLEN / CH;
    for (int c = 0; c < NCHUNK; c++) {
        const int buf = c & 1;
        // prefetch next chunk into registers (latency overlapped with compute)
        float4 v0, v1; float sval = 0.f;
        const bool more = (c + 1 < NCHUNK);
        if (more) {
            v0 = *reinterpret_cast<const float4*>(g_ptr(tid, c + 1));
            if (tid < 128) v1 = *reinterpret_cast<const float4*>(g_ptr(tid + 256, c + 1));
            if (tid < 16) {
                int l8 = tid >> 1;
                size_t row = rowbase + (size_t)(c + 1) * CH + l8;
                sval = (tid & 1) ? dAv[row * NHEADS + h] : dtv[row * NHEADS + h];
            }
        }
        // 8 steps, no syncthreads
        #pragma unroll
        for (int l = 0; l < CH; l++) {
            const float dt_t = sdt[buf][l];
            const float dA_t = sdA[buf][l];
            const float dtx  = dt_t * sx[buf][l][p];
            const float4* Bp = reinterpret_cast<const float4*>(&sB[buf][l][nb]);
            const float4* Cp = reinterpret_cast<const float4*>(&sC[buf][l][nb]);
            float a0 = 0.f, a1 = 0.f;
            #pragma unroll
            for (int i4 = 0; i4 < 4; i4++) {
                float4 Bv = Bp[i4];
                float4 Cv = Cp[i4];
                st[i4*4+0] = fmaf(st[i4*4+0], dA_t, dtx * Bv.x); a0 = fmaf(st[i4*4+0], Cv.x, a0);
                st[i4*4+1] = fmaf(st[i4*4+1], dA_t, dtx * Bv.y); a1 = fmaf(st[i4*4+1], Cv.y, a1);
                st[i4*4+2] = fmaf(st[i4*4+2], dA_t, dtx * Bv.z); a0 = fmaf(st[i4*4+2], Cv.z, a0);
                st[i4*4+3] = fmaf(st[i4*4+3], dA_t, dtx * Bv.w); a1 = fmaf(st[i4*4+3], Cv.w, a1);
            }
            sacc[l][tid] = a0 + a1;
        }
        __syncthreads();
        // reduce + write y for the whole chunk (512 outputs, 2 per thread)
        #pragma unroll
        for (int j = 0; j < 2; j++) {
            int idx = tid + j * 256;
            int l = idx >> 6, pp = idx & 63;
            float yv = sacc[l][pp] + sacc[l][pp + 64] + sacc[l][pp + 128] + sacc[l][pp + 192]
                     + Dh * sx[buf][l][pp];
            y[(rowbase + (size_t)c * CH + l) * D_INNER + h * HEADDIM + pp] = yv;
        }
        // store prefetched chunk
        if (more) {
            *reinterpret_cast<float4*>(s_ptr(tid, buf ^ 1)) = v0;
            if (tid < 128) *reinterpret_cast<float4*>(s_ptr(tid + 256, buf ^ 1)) = v1;
            if (tid < 16) {
                int l8 = tid >> 1;
                if (tid & 1) sdA[buf ^ 1][l8] = sval;
                else         sdt[buf ^ 1][l8] = sval;
            }
        }
        __syncthreads();
    }
}

// ---------------- gate (y * silu(z)) + RMSNorm -> bf16 hi/lo ----------------
__global__ __launch_bounds__(256) void gate_rmsnorm(
    const float* __restrict__ yraw,
    const float* __restrict__ zx,
    const float* __restrict__ norm_w,
    __nv_bfloat16* __restrict__ out_hi,
    __nv_bfloat16* __restrict__ out_lo)
{
    const int row = blockIdx.x;
    const int tid = threadIdx.x;
    const float* yr = yraw + (size_t)row * D_INNER;
    const float* z  = zx + (size_t)row * D_IN_PROJ;

    float v[8];
    float ss = 0.f;
    #pragma unroll
    for (int i = 0; i < 8; i++) {
        int c = tid + i * 256;
        float zz = z[c];
        float g  = zz / (1.f + expf(-zz));
        float t  = yr[c] * g;
        v[i] = t;
        ss = fmaf(t, t, ss);
    }
    #pragma unroll
    for (int off = 16; off > 0; off >>= 1)
        ss += __shfl_xor_sync(0xffffffffu, ss, off);
    __shared__ float swarp[8];
    __shared__ float stot;
    if ((tid & 31) == 0) swarp[tid >> 5] = ss;
    __syncthreads();
    if (tid == 0) {
        float t = 0.f;
        #pragma unroll
        for (int i = 0; i < 8; i++) t += swarp[i];
        stot = t;
    }
    __syncthreads();
    const float scale = rsqrtf(stot * (1.f / D_INNER) + 1e-5f);
    #pragma unroll
    for (int i = 0; i < 8; i++) {
        int c = tid + i * 256;
        float t = v[i] * scale * norm_w[c];
        __nv_bfloat16 h = __float2bfloat16(t);
        out_hi[(size_t)row * D_INNER + c] = h;
        out_lo[(size_t)row * D_INNER + c] = __float2bfloat16(t - __bfloat162float(h));
    }
}

// ---------------- launcher ----------------
extern "C" void kernel_launch(void* const* d_in, const int* in_sizes, int n_in,
                              void* d_out, int out_size)
{
    const float* u       = (const float*)d_in[0];
    const float* W_in    = (const float*)d_in[1];
    const float* conv_w  = (const float*)d_in[2];
    const float* conv_b  = (const float*)d_in[3];
    const float* dt_bias = (const float*)d_in[4];
    const float* A_log   = (const float*)d_in[5];
    const float* Dp      = (const float*)d_in[6];
    const float* norm_w  = (const float*)d_in[7];
    const float* W_out   = (const float*)d_in[8];
    float* out = (float*)d_out;

    float *zx, *cv, *dtp, *dAp, *yp;
    __nv_bfloat16 *uhi, *ulo, *wih, *wil, *woh, *wol, *ynh, *ynl;
    cudaGetSymbolAddress((void**)&zx,  g_zx);
    cudaGetSymbolAddress((void**)&cv,  g_conv);
    cudaGetSymbolAddress((void**)&dtp, g_dt);
    cudaGetSymbolAddress((void**)&dAp, g_dA);
    cudaGetSymbolAddress((void**)&yp,  g_y);
    cudaGetSymbolAddress((void**)&uhi, g_u_hi);
    cudaGetSymbolAddress((void**)&ulo, g_u_lo);
    cudaGetSymbolAddress((void**)&wih, g_wint_hi);
    cudaGetSymbolAddress((void**)&wil, g_wint_lo);
    cudaGetSymbolAddress((void**)&woh, g_woutt_hi);
    cudaGetSymbolAddress((void**)&wol, g_woutt_lo);
    cudaGetSymbolAddress((void**)&ynh, g_yn_hi);
    cudaGetSymbolAddress((void**)&ynl, g_yn_lo);

    cudaFuncSetAttribute(gemm_mma, cudaFuncAttributeMaxDynamicSharedMemorySize, GEMM_SMEM);

    // operand prep
    {
        int n4 = ROWS * D_MODEL / 4;
        convert_split<<<(n4 + 255) / 256, 256>>>((const float4*)u, uhi, ulo, n4);
    }
    transpose_split<<<dim3(NP1 / 32, D_MODEL / 32), 256>>>(W_in, D_MODEL, D_IN_PROJ, wih, wil);
    transpose_split<<<dim3(D_MODEL / 32, D_INNER / 32), 256>>>(W_out, D_INNER, D_MODEL, woh, wol);

    // 1) zxbcdt = u @ W_in
    gemm_mma<<<dim3(NP1 / 128, ROWS / 128), 256, GEMM_SMEM>>>(
        uhi, ulo, wih, wil, zx, D_MODEL, D_IN_PROJ, D_IN_PROJ);

    // 2) dt / dA
    prep_dt<<<(ROWS * NHEADS + 255) / 256, 256>>>(zx, dt_bias, A_log, dtp, dAp);
    // 3) depthwise conv + silu
    conv_silu2<<<ROWS, 256>>>(zx, conv_w, conv_b, cv);
    // 4) selective scan (+ x*D)
    ssm_scan3<<<B_SZ * NHEADS, 256>>>(cv, dtp, dAp, Dp, yp);
    // 5) gate + rmsnorm -> bf16 hi/lo
    gate_rmsnorm<<<ROWS, 256>>>(yp, zx, norm_w, ynh, ynl);
    // 6) out = yn @ W_out
    gemm_mma<<<dim3(D_MODEL / 128, ROWS / 128), 256, GEMM_SMEM>>>(
        ynh, ynl, woh, wol, out, D_INNER, D_MODEL, D_MODEL);
}

// round 6
// speedup vs baseline: 3.0069x; 1.0831x over previous
#include <cuda_runtime.h>
#include <cuda_bf16.h>
#include <cstdint>

// ---------------- problem constants ----------------
#define D_MODEL   1024
#define D_STATE   64
#define D_CONV    4
#define HEADDIM   64
#define D_INNER   2048
#define NHEADS    32
#define CONV_DIM  2176            // D_INNER + 2*D_STATE
#define D_IN_PROJ 4256            // 2*D_INNER + 2*D_STATE + NHEADS
#define B_SZ      4
#define SEQLEN    2048
#define ROWS      (B_SZ * SEQLEN) // 8192
#define NP1       4352            // D_IN_PROJ padded to 128

// ---------------- scratch (static device memory) ----------------
__device__ float g_zx[(size_t)ROWS * D_IN_PROJ];   // u @ W_in (fp32)
__device__ float g_conv[(size_t)ROWS * CONV_DIM];  // conv+silu output
__device__ float g_dt[(size_t)ROWS * NHEADS];
__device__ float g_dA[(size_t)ROWS * NHEADS];
__device__ float g_y[(size_t)ROWS * D_INNER];      // scan output (+ x*D)

__device__ __nv_bfloat16 g_u_hi[(size_t)ROWS * D_MODEL];
__device__ __nv_bfloat16 g_u_lo[(size_t)ROWS * D_MODEL];
__device__ __nv_bfloat16 g_wint_hi[(size_t)NP1 * D_MODEL];      // W_in^T padded [NP1, 1024]
__device__ __nv_bfloat16 g_wint_lo[(size_t)NP1 * D_MODEL];
__device__ __nv_bfloat16 g_woutt_hi[(size_t)D_MODEL * D_INNER]; // W_out^T [1024, 2048]
__device__ __nv_bfloat16 g_woutt_lo[(size_t)D_MODEL * D_INNER];
__device__ __nv_bfloat16 g_yn_hi[(size_t)ROWS * D_INNER];
__device__ __nv_bfloat16 g_yn_lo[(size_t)ROWS * D_INNER];

// ================= low-level helpers (arch-neutral PTX: sm_80+) =================
__device__ __forceinline__ uint32_t smem_u32(const void* p) {
    uint32_t a;
    asm("{ .reg .u64 t; cvta.to.shared.u64 t, %1; cvt.u32.u64 %0, t; }" : "=r"(a) : "l"(p));
    return a;
}
__device__ __forceinline__ void cp_async16(uint32_t sdst, const void* gsrc) {
    asm volatile("cp.async.cg.shared.global [%0], [%1], 16;" :: "r"(sdst), "l"(gsrc));
}
__device__ __forceinline__ void cp_commit() {
    asm volatile("cp.async.commit_group;" ::: "memory");
}
__device__ __forceinline__ void cp_wait1() {
    asm volatile("cp.async.wait_group 1;" ::: "memory");
}
__device__ __forceinline__ void ldsm_x4(uint32_t& r0, uint32_t& r1, uint32_t& r2, uint32_t& r3,
                                        uint32_t addr) {
    asm volatile("ldmatrix.sync.aligned.m8n8.x4.shared.b16 {%0,%1,%2,%3}, [%4];"
                 : "=r"(r0), "=r"(r1), "=r"(r2), "=r"(r3) : "r"(addr));
}
__device__ __forceinline__ void mma16816(float& d0, float& d1, float& d2, float& d3,
                                         uint32_t a0, uint32_t a1, uint32_t a2, uint32_t a3,
                                         uint32_t b0, uint32_t b1) {
    asm volatile(
        "mma.sync.aligned.m16n8k16.row.col.f32.bf16.bf16.f32 "
        "{%0,%1,%2,%3}, {%4,%5,%6,%7}, {%8,%9}, {%0,%1,%2,%3};"
        : "+f"(d0), "+f"(d1), "+f"(d2), "+f"(d3)
        : "r"(a0), "r"(a1), "r"(a2), "r"(a3), "r"(b0), "r"(b1));
}

// ================= split-bf16 HMMA GEMM (2-stage pipeline, 2 CTAs/SM) =================
#define LDSB   80                       // smem row stride in bytes (32 bf16 + pad)
#define TILE_B (128 * LDSB)             // 10240 B per operand tile
#define STAGE_B (4 * TILE_B)            // 40960 B per stage (Ahi,Alo,Bhi,Blo)
#define NSTAGE 2
#define GEMM_SMEM (NSTAGE * STAGE_B)    // 81920 B

__global__ __launch_bounds__(256, 2) void gemm_mma(
    const __nv_bfloat16* __restrict__ Ahi, const __nv_bfloat16* __restrict__ Alo,
    const __nv_bfloat16* __restrict__ Bhi, const __nv_bfloat16* __restrict__ Blo,
    float* __restrict__ C, int K, int Nout, int ldc)
{
    extern __shared__ __align__(16) char smem[];
    const uint32_t sbase = smem_u32(smem);

    const int tid  = threadIdx.x;
    const int lane = tid & 31;
    const int wid  = tid >> 5;
    const int wm   = wid & 1;      // 0..1 -> 64-row block
    const int wn   = wid >> 1;     // 0..3 -> 32-col block
    const int Mbase = blockIdx.y * 128;
    const int Nbase = blockIdx.x * 128;

    const __nv_bfloat16* srcs[4];
    srcs[0] = Ahi + (size_t)Mbase * K;
    srcs[1] = Alo + (size_t)Mbase * K;
    srcs[2] = Bhi + (size_t)Nbase * K;
    srcs[3] = Blo + (size_t)Nbase * K;

    const int lr = tid >> 2;       // 0..63 (row pair base)
    const int lc = tid & 3;        // 0..3  (16B chunk)

    auto issue = [&](int kt, int s) {
        const uint32_t sb = sbase + (uint32_t)s * STAGE_B;
        #pragma unroll
        for (int op = 0; op < 4; op++) {
            const __nv_bfloat16* src = srcs[op] + (size_t)kt * 32 + lc * 8;
            const uint32_t dst = sb + (uint32_t)op * TILE_B + lc * 16;
            #pragma unroll
            for (int h = 0; h < 2; h++) {
                int r = lr + h * 64;
                cp_async16(dst + (uint32_t)r * LDSB, src + (size_t)r * K);
            }
        }
    };

    float acc[4][4][4];
    #pragma unroll
    for (int m = 0; m < 4; m++)
        #pragma unroll
        for (int n = 0; n < 4; n++)
            #pragma unroll
            for (int e = 0; e < 4; e++) acc[m][n][e] = 0.f;

    const int KT = K / 32;
    issue(0, 0); cp_commit();
    issue(1, 1); cp_commit();

    const int a_row = (lane & 15);
    const int a_k16 = (lane >> 4) * 16;
    const int b_row = (lane & 7) + ((lane >> 4) & 1) * 8;
    const int b_k16 = ((lane >> 3) & 1) * 16;

    for (int kt = 0; kt < KT; kt++) {
        cp_wait1();
        __syncthreads();
        const uint32_t sb = sbase + (uint32_t)(kt & 1) * STAGE_B;
        const uint32_t sAhi = sb;
        const uint32_t sAlo = sb + TILE_B;
        const uint32_t sBhi = sb + 2 * TILE_B;
        const uint32_t sBlo = sb + 3 * TILE_B;

        #pragma unroll
        for (int ks = 0; ks < 2; ks++) {
            const uint32_t koff = (uint32_t)ks * 32;

            uint32_t ah[4][4], al[4][4];
            #pragma unroll
            for (int mt = 0; mt < 4; mt++) {
                const uint32_t rowoff = (uint32_t)(wm * 64 + mt * 16 + a_row) * LDSB + koff + a_k16;
                ldsm_x4(ah[mt][0], ah[mt][1], ah[mt][2], ah[mt][3], sAhi + rowoff);
                ldsm_x4(al[mt][0], al[mt][1], al[mt][2], al[mt][3], sAlo + rowoff);
            }
            uint32_t bh[4][2], bl[4][2];
            #pragma unroll
            for (int np = 0; np < 2; np++) {
                const uint32_t rowoff = (uint32_t)(wn * 32 + np * 16 + b_row) * LDSB + koff + b_k16;
                ldsm_x4(bh[np*2][0], bh[np*2][1], bh[np*2+1][0], bh[np*2+1][1], sBhi + rowoff);
                ldsm_x4(bl[np*2][0], bl[np*2][1], bl[np*2+1][0], bl[np*2+1][1], sBlo + rowoff);
            }
            #pragma unroll
            for (int mt = 0; mt < 4; mt++)
                #pragma unroll
                for (int nt = 0; nt < 4; nt++) {
                    float* d = acc[mt][nt];
                    mma16816(d[0], d[1], d[2], d[3],
                             ah[mt][0], ah[mt][1], ah[mt][2], ah[mt][3], bh[nt][0], bh[nt][1]);
                    mma16816(d[0], d[1], d[2], d[3],
                             ah[mt][0], ah[mt][1], ah[mt][2], ah[mt][3], bl[nt][0], bl[nt][1]);
                    mma16816(d[0], d[1], d[2], d[3],
                             al[mt][0], al[mt][1], al[mt][2], al[mt][3], bh[nt][0], bh[nt][1]);
                }
        }
        __syncthreads();
        if (kt + 2 < KT) issue(kt + 2, kt & 1);
        cp_commit();
    }

    #pragma unroll
    for (int mt = 0; mt < 4; mt++) {
        const int row0 = Mbase + wm * 64 + mt * 16 + (lane >> 2);
        #pragma unroll
        for (int nt = 0; nt < 4; nt++) {
            const int col = Nbase + wn * 32 + nt * 8 + (lane & 3) * 2;
            if (col < Nout) {
                float2 v0 = make_float2(acc[mt][nt][0], acc[mt][nt][1]);
                float2 v1 = make_float2(acc[mt][nt][2], acc[mt][nt][3]);
                *reinterpret_cast<float2*>(C + (size_t)row0 * ldc + col) = v0;
                *reinterpret_cast<float2*>(C + (size_t)(row0 + 8) * ldc + col) = v1;
            }
        }
    }
}

// ================= conversions =================
__global__ void convert_split(const float4* __restrict__ in,
                              __nv_bfloat16* __restrict__ hi,
                              __nv_bfloat16* __restrict__ lo, int n4)
{
    int i = blockIdx.x * blockDim.x + threadIdx.x;
    if (i >= n4) return;
    float4 v = in[i];
    __nv_bfloat16 h[4], l[4];
    float f[4] = {v.x, v.y, v.z, v.w};
    #pragma unroll
    for (int j = 0; j < 4; j++) {
        h[j] = __float2bfloat16(f[j]);
        l[j] = __float2bfloat16(f[j] - __bfloat162float(h[j]));
    }
    *reinterpret_cast<uint2*>(hi + (size_t)i * 4) = *reinterpret_cast<uint2*>(h);
    *reinterpret_cast<uint2*>(lo + (size_t)i * 4) = *reinterpret_cast<uint2*>(l);
}

__global__ __launch_bounds__(256) void transpose_split(
    const float* __restrict__ W, int K, int N,
    __nv_bfloat16* __restrict__ Thi, __nv_bfloat16* __restrict__ Tlo)
{
    __shared__ float t[32][33];
    const int n0 = blockIdx.x * 32, k0 = blockIdx.y * 32;
    const int tx = threadIdx.x & 31, ty = threadIdx.x >> 5;
    #pragma unroll
    for (int j = 0; j < 4; j++) {
        int k = k0 + ty + j * 8;
        int n = n0 + tx;
        t[ty + j * 8][tx] = (n < N) ? W[(size_t)k * N + n] : 0.f;
    }
    __syncthreads();
    #pragma unroll
    for (int j = 0; j < 4; j++) {
        int n = n0 + ty + j * 8;
        int k = k0 + tx;
        float v = t[tx][ty + j * 8];
        __nv_bfloat16 h = __float2bfloat16(v);
        Thi[(size_t)n * K + k] = h;
        Tlo[(size_t)n * K + k] = __float2bfloat16(v - __bfloat162float(h));
    }
}

// ---------------- dt / dA precompute ----------------
__global__ void prep_dt(const float* __restrict__ zx,
                        const float* __restrict__ dt_bias,
                        const float* __restrict__ A_log,
                        float* __restrict__ dt_out,
                        float* __restrict__ dA_out)
{
    int idx = blockIdx.x * blockDim.x + threadIdx.x;
    if (idx >= ROWS * NHEADS) return;
    int h = idx & (NHEADS - 1);
    int row = idx >> 5;
    float v = zx[(size_t)row * D_IN_PROJ + (D_IN_PROJ - NHEADS) + h] + dt_bias[h];
    float dt = (v > 0.f) ? (v + log1pf(expf(-v))) : log1pf(expf(v));
    float A = -expf(A_log[h]);
    dt_out[idx] = dt;
    dA_out[idx] = expf(dt * A);
}

// ---------------- depthwise causal conv1d + SiLU (coalesced float4) ----------------
__global__ __launch_bounds__(256) void conv_silu2(
    const float* __restrict__ zx,
    const float* __restrict__ conv_w,
    const float* __restrict__ conv_b,
    float* __restrict__ out)
{
    const int row = blockIdx.x;
    const int l   = row & (SEQLEN - 1);
    const float* base = zx + (size_t)row * D_IN_PROJ + D_INNER;
    float* orow = out + (size_t)row * CONV_DIM;

    for (int c4 = threadIdx.x; c4 < CONV_DIM / 4; c4 += 256) {
        const int c = c4 * 4;
        float4 acc = *reinterpret_cast<const float4*>(conv_b + c);
        #pragma unroll
        for (int k = 0; k < D_CONV; k++) {
            int dl = l - (D_CONV - 1) + k;
            if (dl >= 0) {
                float4 w = *reinterpret_cast<const float4*>(conv_w + k * CONV_DIM + c);
                float4 v = *reinterpret_cast<const float4*>(
                    base + (long)(k - (D_CONV - 1)) * D_IN_PROJ + c);
                acc.x = fmaf(w.x, v.x, acc.x);
                acc.y = fmaf(w.y, v.y, acc.y);
                acc.z = fmaf(w.z, v.z, acc.z);
                acc.w = fmaf(w.w, v.w, acc.w);
            }
        }
        acc.x = acc.x / (1.f + expf(-acc.x));
        acc.y = acc.y / (1.f + expf(-acc.y));
        acc.z = acc.z / (1.f + expf(-acc.z));
        acc.w = acc.w / (1.f + expf(-acc.w));
        *reinterpret_cast<float4*>(orow + c) = acc;
    }
}

// ---------------- selective scan: 256 threads, chunked, sync-free inner loop ----------------
#define CH 8
__global__ __launch_bounds__(256) void ssm_scan3(
    const float* __restrict__ conv, const float* __restrict__ dtv,
    const float* __restrict__ dAv, const float* __restrict__ Dparm,
    float* __restrict__ y)
{
    const int b = blockIdx.x >> 5;
    const int h = blockIdx.x & 31;
    const int tid = threadIdx.x;
    const int p = tid & 63;
    const int g = tid >> 6;           // 0..3, states [g*16, g*16+16)
    const int nb = g * 16;

    __shared__ __align__(16) float sx[2][CH][64];
    __shared__ __align__(16) float sB[2][CH][64];
    __shared__ __align__(16) float sC[2][CH][64];
    __shared__ float sdt[2][CH], sdA[2][CH];
    __shared__ __align__(16) float sacc[CH][256];

    float st[16];
    #pragma unroll
    for (int i = 0; i < 16; i++) st[i] = 0.f;
    const float Dh = Dparm[h];
    const size_t rowbase = (size_t)b * SEQLEN;

    auto g_ptr = [&](int slot, int chunk) -> const float* {
        int l8 = slot / 48; int rem = slot % 48; int a = rem >> 4; int q = rem & 15;
        size_t row = rowbase + (size_t)chunk * CH + l8;
        int off = (a == 0) ? h * HEADDIM : (a == 1) ? D_INNER : (D_INNER + D_STATE);
        return conv + row * CONV_DIM + off + q * 4;
    };
    auto s_ptr = [&](int slot, int buf) -> float* {
        int l8 = slot / 48; int rem = slot % 48; int a = rem >> 4; int q = rem & 15;
        float* base = (a == 0) ? &sx[buf][l8][0] : (a == 1) ? &sB[buf][l8][0] : &sC[buf][l8][0];
        return base + q * 4;
    };

    // preload chunk 0
    {
        float4 v0 = *reinterpret_cast<const float4*>(g_ptr(tid, 0));
        *reinterpret_cast<float4*>(s_ptr(tid, 0)) = v0;
        if (tid < 128) {
            float4 v1 = *reinterpret_cast<const float4*>(g_ptr(tid + 256, 0));
            *reinterpret_cast<float4*>(s_ptr(tid + 256, 0)) = v1;
        }
        if (tid < 16) {
            int l8 = tid >> 1;
            size_t row = rowbase + l8;
            if (tid & 1) sdA[0][l8] = dAv[row * NHEADS + h];
            else         sdt[0][l8] = dtv[row * NHEADS + h];
        }
        __syncthreads();
    }

    const int NCHUNK = SEQLEN / CH;
    for (int c = 0; c < NCHUNK; c++) {
        const int buf = c & 1;
        float4 v0, v1; float sval = 0.f;
        const bool more = (c + 1 < NCHUNK);
        if (more) {
            v0 = *reinterpret_cast<const float4*>(g_ptr(tid, c + 1));
            if (tid < 128) v1 = *reinterpret_cast<const float4*>(g_ptr(tid + 256, c + 1));
            if (tid < 16) {
                int l8 = tid >> 1;
                size_t row = rowbase + (size_t)(c + 1) * CH + l8;
                sval = (tid & 1) ? dAv[row * NHEADS + h] : dtv[row * NHEADS + h];
            }
        }
        #pragma unroll
        for (int l = 0; l < CH; l++) {
            const float dt_t = sdt[buf][l];
            const float dA_t = sdA[buf][l];
            const float dtx  = dt_t * sx[buf][l][p];
            const float4* Bp = reinterpret_cast<const float4*>(&sB[buf][l][nb]);
            const float4* Cp = reinterpret_cast<const float4*>(&sC[buf][l][nb]);
            float a0 = 0.f, a1 = 0.f;
            #pragma unroll
            for (int i4 = 0; i4 < 4; i4++) {
                float4 Bv = Bp[i4];
                float4 Cv = Cp[i4];
                st[i4*4+0] = fmaf(st[i4*4+0], dA_t, dtx * Bv.x); a0 = fmaf(st[i4*4+0], Cv.x, a0);
                st[i4*4+1] = fmaf(st[i4*4+1], dA_t, dtx * Bv.y); a1 = fmaf(st[i4*4+1], Cv.y, a1);
                st[i4*4+2] = fmaf(st[i4*4+2], dA_t, dtx * Bv.z); a0 = fmaf(st[i4*4+2], Cv.z, a0);
                st[i4*4+3] = fmaf(st[i4*4+3], dA_t, dtx * Bv.w); a1 = fmaf(st[i4*4+3], Cv.w, a1);
            }
            sacc[l][tid] = a0 + a1;
        }
        __syncthreads();
        #pragma unroll
        for (int j = 0; j < 2; j++) {
            int idx = tid + j * 256;
            int l = idx >> 6, pp = idx & 63;
            float yv = sacc[l][pp] + sacc[l][pp + 64] + sacc[l][pp + 128] + sacc[l][pp + 192]
                     + Dh * sx[buf][l][pp];
            y[(rowbase + (size_t)c * CH + l) * D_INNER + h * HEADDIM + pp] = yv;
        }
        if (more) {
            *reinterpret_cast<float4*>(s_ptr(tid, buf ^ 1)) = v0;
            if (tid < 128) *reinterpret_cast<float4*>(s_ptr(tid + 256, buf ^ 1)) = v1;
            if (tid < 16) {
                int l8 = tid >> 1;
                if (tid & 1) sdA[buf ^ 1][l8] = sval;
                else         sdt[buf ^ 1][l8] = sval;
            }
        }
        __syncthreads();
    }
}

// ---------------- gate (y * silu(z)) + RMSNorm -> bf16 hi/lo ----------------
__global__ __launch_bounds__(256) void gate_rmsnorm(
    const float* __restrict__ yraw,
    const float* __restrict__ zx,
    const float* __restrict__ norm_w,
    __nv_bfloat16* __restrict__ out_hi,
    __nv_bfloat16* __restrict__ out_lo)
{
    const int row = blockIdx.x;
    const int tid = threadIdx.x;
    const float* yr = yraw + (size_t)row * D_INNER;
    const float* z  = zx + (size_t)row * D_IN_PROJ;

    float v[8];
    float ss = 0.f;
    #pragma unroll
    for (int i = 0; i < 8; i++) {
        int c = tid + i * 256;
        float zz = z[c];
        float g  = zz / (1.f + expf(-zz));
        float t  = yr[c] * g;
        v[i] = t;
        ss = fmaf(t, t, ss);
    }
    #pragma unroll
    for (int off = 16; off > 0; off >>= 1)
        ss += __shfl_xor_sync(0xffffffffu, ss, off);
    __shared__ float swarp[8];
    __shared__ float stot;
    if ((tid & 31) == 0) swarp[tid >> 5] = ss;
    __syncthreads();
    if (tid == 0) {
        float t = 0.f;
        #pragma unroll
        for (int i = 0; i < 8; i++) t += swarp[i];
        stot = t;
    }
    __syncthreads();
    const float scale = rsqrtf(stot * (1.f / D_INNER) + 1e-5f);
    #pragma unroll
    for (int i = 0; i < 8; i++) {
        int c = tid + i * 256;
        float t = v[i] * scale * norm_w[c];
        __nv_bfloat16 h = __float2bfloat16(t);
        out_hi[(size_t)row * D_INNER + c] = h;
        out_lo[(size_t)row * D_INNER + c] = __float2bfloat16(t - __bfloat162float(h));
    }
}

// ---------------- launcher ----------------
extern "C" void kernel_launch(void* const* d_in, const int* in_sizes, int n_in,
                              void* d_out, int out_size)
{
    const float* u       = (const float*)d_in[0];
    const float* W_in    = (const float*)d_in[1];
    const float* conv_w  = (const float*)d_in[2];
    const float* conv_b  = (const float*)d_in[3];
    const float* dt_bias = (const float*)d_in[4];
    const float* A_log   = (const float*)d_in[5];
    const float* Dp      = (const float*)d_in[6];
    const float* norm_w  = (const float*)d_in[7];
    const float* W_out   = (const float*)d_in[8];
    float* out = (float*)d_out;

    float *zx, *cv, *dtp, *dAp, *yp;
    __nv_bfloat16 *uhi, *ulo, *wih, *wil, *woh, *wol, *ynh, *ynl;
    cudaGetSymbolAddress((void**)&zx,  g_zx);
    cudaGetSymbolAddress((void**)&cv,  g_conv);
    cudaGetSymbolAddress((void**)&dtp, g_dt);
    cudaGetSymbolAddress((void**)&dAp, g_dA);
    cudaGetSymbolAddress((void**)&yp,  g_y);
    cudaGetSymbolAddress((void**)&uhi, g_u_hi);
    cudaGetSymbolAddress((void**)&ulo, g_u_lo);
    cudaGetSymbolAddress((void**)&wih, g_wint_hi);
    cudaGetSymbolAddress((void**)&wil, g_wint_lo);
    cudaGetSymbolAddress((void**)&woh, g_woutt_hi);
    cudaGetSymbolAddress((void**)&wol, g_woutt_lo);
    cudaGetSymbolAddress((void**)&ynh, g_yn_hi);
    cudaGetSymbolAddress((void**)&ynl, g_yn_lo);

    cudaFuncSetAttribute(gemm_mma, cudaFuncAttributeMaxDynamicSharedMemorySize, GEMM_SMEM);

    // operand prep
    {
        int n4 = ROWS * D_MODEL / 4;
        convert_split<<<(n4 + 255) / 256, 256>>>((const float4*)u, uhi, ulo, n4);
    }
    transpose_split<<<dim3(NP1 / 32, D_MODEL / 32), 256>>>(W_in, D_MODEL, D_IN_PROJ, wih, wil);
    transpose_split<<<dim3(D_MODEL / 32, D_INNER / 32), 256>>>(W_out, D_INNER, D_MODEL, woh, wol);

    // 1) zxbcdt = u @ W_in
    gemm_mma<<<dim3(NP1 / 128, ROWS / 128), 256, GEMM_SMEM>>>(
        uhi, ulo, wih, wil, zx, D_MODEL, D_IN_PROJ, D_IN_PROJ);

    // 2) dt / dA
    prep_dt<<<(ROWS * NHEADS + 255) / 256, 256>>>(zx, dt_bias, A_log, dtp, dAp);
    // 3) depthwise conv + silu
    conv_silu2<<<ROWS, 256>>>(zx, conv_w, conv_b, cv);
    // 4) selective scan (+ x*D)
    ssm_scan3<<<B_SZ * NHEADS, 256>>>(cv, dtp, dAp, Dp, yp);
    // 5) gate + rmsnorm -> bf16 hi/lo
    gate_rmsnorm<<<ROWS, 256>>>(yp, zx, norm_w, ynh, ynl);
    // 6) out = yn @ W_out
    gemm_mma<<<dim3(D_MODEL / 128, ROWS / 128), 256, GEMM_SMEM>>>(
        ynh, ynl, woh, wol, out, D_INNER, D_MODEL, D_MODEL);
}

// round 7
// speedup vs baseline: 3.4756x; 1.1559x over previous
#include <cuda_runtime.h>
#include <cuda_bf16.h>
#include <cstdint>

// ---------------- problem constants ----------------
#define D_MODEL   1024
#define D_STATE   64
#define D_CONV    4
#define HEADDIM   64
#define D_INNER   2048
#define NHEADS    32
#define CONV_DIM  2176            // D_INNER + 2*D_STATE
#define D_IN_PROJ 4256            // 2*D_INNER + 2*D_STATE + NHEADS
#define B_SZ      4
#define SEQLEN    2048
#define ROWS      (B_SZ * SEQLEN) // 8192
#define NP1       4352            // D_IN_PROJ padded to 128

// ---------------- scratch (static device memory) ----------------
__device__ float g_zx[(size_t)ROWS * D_IN_PROJ];   // u @ W_in (fp32)
__device__ float g_conv[(size_t)ROWS * CONV_DIM];  // conv+silu output
__device__ float g_dt[(size_t)ROWS * NHEADS];
__device__ float g_dA[(size_t)ROWS * NHEADS];
__device__ float g_y[(size_t)ROWS * D_INNER];      // scan output (+ x*D)

__device__ __nv_bfloat16 g_u_hi[(size_t)ROWS * D_MODEL];
__device__ __nv_bfloat16 g_u_lo[(size_t)ROWS * D_MODEL];
__device__ __nv_bfloat16 g_wint_hi[(size_t)NP1 * D_MODEL];      // W_in^T padded [NP1, 1024]
__device__ __nv_bfloat16 g_wint_lo[(size_t)NP1 * D_MODEL];
__device__ __nv_bfloat16 g_woutt_hi[(size_t)D_MODEL * D_INNER]; // W_out^T [1024, 2048]
__device__ __nv_bfloat16 g_woutt_lo[(size_t)D_MODEL * D_INNER];
__device__ __nv_bfloat16 g_yn_hi[(size_t)ROWS * D_INNER];
__device__ __nv_bfloat16 g_yn_lo[(size_t)ROWS * D_INNER];

// ================= low-level helpers (arch-neutral PTX: sm_80+) =================
__device__ __forceinline__ uint32_t smem_u32(const void* p) {
    uint32_t a;
    asm("{ .reg .u64 t; cvta.to.shared.u64 t, %1; cvt.u32.u64 %0, t; }" : "=r"(a) : "l"(p));
    return a;
}
__device__ __forceinline__ void cp_async16(uint32_t sdst, const void* gsrc) {
    asm volatile("cp.async.cg.shared.global [%0], [%1], 16;" :: "r"(sdst), "l"(gsrc));
}
__device__ __forceinline__ void cp_commit() {
    asm volatile("cp.async.commit_group;" ::: "memory");
}
__device__ __forceinline__ void cp_wait1() {
    asm volatile("cp.async.wait_group 1;" ::: "memory");
}
__device__ __forceinline__ void ldsm_x4(uint32_t& r0, uint32_t& r1, uint32_t& r2, uint32_t& r3,
                                        uint32_t addr) {
    asm volatile("ldmatrix.sync.aligned.m8n8.x4.shared.b16 {%0,%1,%2,%3}, [%4];"
                 : "=r"(r0), "=r"(r1), "=r"(r2), "=r"(r3) : "r"(addr));
}
__device__ __forceinline__ void mma16816(float& d0, float& d1, float& d2, float& d3,
                                         uint32_t a0, uint32_t a1, uint32_t a2, uint32_t a3,
                                         uint32_t b0, uint32_t b1) {
    asm volatile(
        "mma.sync.aligned.m16n8k16.row.col.f32.bf16.bf16.f32 "
        "{%0,%1,%2,%3}, {%4,%5,%6,%7}, {%8,%9}, {%0,%1,%2,%3};"
        : "+f"(d0), "+f"(d1), "+f"(d2), "+f"(d3)
        : "r"(a0), "r"(a1), "r"(a2), "r"(a3), "r"(b0), "r"(b1));
}

// ================= split-bf16 HMMA GEMM =================
// 64B smem rows with XOR chunk swizzle: physical 16B chunk = c ^ ((row>>1)&3).
// Bank-conflict-free ldmatrix, 16B-aligned cp.async, no padding.
// 3-stage pipeline, single __syncthreads per k-tile, 2 CTAs/SM.
#define LDSB   64                       // smem row stride in bytes (32 bf16, exact)
#define TILE_B (128 * LDSB)             // 8192 B per operand tile
#define STAGE_B (4 * TILE_B)            // 32768 B per stage (Ahi,Alo,Bhi,Blo)
#define NSTAGE 3
#define GEMM_SMEM (NSTAGE * STAGE_B)    // 98304 B

__global__ __launch_bounds__(256, 2) void gemm_mma(
    const __nv_bfloat16* __restrict__ Ahi, const __nv_bfloat16* __restrict__ Alo,
    const __nv_bfloat16* __restrict__ Bhi, const __nv_bfloat16* __restrict__ Blo,
    float* __restrict__ C, int K, int Nout, int ldc)
{
    extern __shared__ __align__(16) char smem[];
    const uint32_t sbase = smem_u32(smem);

    const int tid  = threadIdx.x;
    const int lane = tid & 31;
    const int wid  = tid >> 5;
    const int wm   = wid & 1;      // 0..1 -> 64-row block
    const int wn   = wid >> 1;     // 0..3 -> 32-col block
    const int Mbase = blockIdx.y * 128;
    const int Nbase = blockIdx.x * 128;

    const __nv_bfloat16* srcs[4];
    srcs[0] = Ahi + (size_t)Mbase * K;
    srcs[1] = Alo + (size_t)Mbase * K;
    srcs[2] = Bhi + (size_t)Nbase * K;
    srcs[3] = Blo + (size_t)Nbase * K;

    const int lr = tid >> 2;                 // 0..63 (row base)
    const int lc = tid & 3;                  // 0..3  (16B chunk)
    const int st_c = (lc ^ ((lr >> 1) & 3)); // swizzled store chunk (constant per thread)

    auto issue = [&](int kt, int s) {
        const uint32_t sb = sbase + (uint32_t)s * STAGE_B;
        #pragma unroll
        for (int op = 0; op < 4; op++) {
            const __nv_bfloat16* src = srcs[op] + (size_t)kt * 32 + lc * 8;
            const uint32_t dst = sb + (uint32_t)op * TILE_B + (uint32_t)st_c * 16;
            #pragma unroll
            for (int h = 0; h < 2; h++) {
                int r = lr + h * 64;     // (r>>1)&3 identical for r and r+64
                cp_async16(dst + (uint32_t)r * LDSB, src + (size_t)r * K);
            }
        }
    };

    float acc[4][4][4];
    #pragma unroll
    for (int m = 0; m < 4; m++)
        #pragma unroll
        for (int n = 0; n < 4; n++)
            #pragma unroll
            for (int e = 0; e < 4; e++) acc[m][n][e] = 0.f;

    const int KT = K / 32;
    issue(0, 0); cp_commit();
    issue(1, 1); cp_commit();

    // per-lane ldmatrix row/chunk components
    const int a_row = (lane & 15);
    const int a_ch  = (lane >> 4);                          // 0..1 (16B chunk within k16)
    const int a_swz = (a_row >> 1) & 3;                     // row-swizzle (mt*16, wm*64 don't affect)
    const int b_row = (lane & 7) + ((lane >> 4) & 1) * 8;
    const int b_ch  = ((lane >> 3) & 1);
    const int b_swz = (b_row >> 1) & 3;

    int stage = 0;
    for (int kt = 0; kt < KT; kt++) {
        cp_wait1();                 // group kt complete (pending: kt+1)
        __syncthreads();            // all threads waited; prior stage fully consumed
        if (kt + 2 < KT) issue(kt + 2, (stage + 2 >= NSTAGE) ? stage + 2 - NSTAGE : stage + 2);
        cp_commit();

        const uint32_t sb = sbase + (uint32_t)stage * STAGE_B;
        const uint32_t sAhi = sb;
        const uint32_t sAlo = sb + TILE_B;
        const uint32_t sBhi = sb + 2 * TILE_B;
        const uint32_t sBlo = sb + 3 * TILE_B;

        #pragma unroll
        for (int ks = 0; ks < 2; ks++) {
            const int kchunk = ks * 2;   // 32B per k16-step => 2 chunks

            uint32_t ah[4][4], al[4][4];
            #pragma unroll
            for (int mt = 0; mt < 4; mt++) {
                const int row = wm * 64 + mt * 16 + a_row;
                const uint32_t off = (uint32_t)row * LDSB
                                   + (uint32_t)(((kchunk + a_ch) ^ a_swz) << 4);
                ldsm_x4(ah[mt][0], ah[mt][1], ah[mt][2], ah[mt][3], sAhi + off);
                ldsm_x4(al[mt][0], al[mt][1], al[mt][2], al[mt][3], sAlo + off);
            }
            uint32_t bh[4][2], bl[4][2];
            #pragma unroll
            for (int np = 0; np < 2; np++) {
                const int row = wn * 32 + np * 16 + b_row;
                const uint32_t off = (uint32_t)row * LDSB
                                   + (uint32_t)(((kchunk + b_ch) ^ b_swz) << 4);
                ldsm_x4(bh[np*2][0], bh[np*2][1], bh[np*2+1][0], bh[np*2+1][1], sBhi + off);
                ldsm_x4(bl[np*2][0], bl[np*2][1], bl[np*2+1][0], bl[np*2+1][1], sBlo + off);
            }
            #pragma unroll
            for (int mt = 0; mt < 4; mt++)
                #pragma unroll
                for (int nt = 0; nt < 4; nt++) {
                    float* d = acc[mt][nt];
                    mma16816(d[0], d[1], d[2], d[3],
                             ah[mt][0], ah[mt][1], ah[mt][2], ah[mt][3], bh[nt][0], bh[nt][1]);
                    mma16816(d[0], d[1], d[2], d[3],
                             ah[mt][0], ah[mt][1], ah[mt][2], ah[mt][3], bl[nt][0], bl[nt][1]);
                    mma16816(d[0], d[1], d[2], d[3],
                             al[mt][0], al[mt][1], al[mt][2], al[mt][3], bh[nt][0], bh[nt][1]);
                }
        }
        stage = (stage == NSTAGE - 1) ? 0 : stage + 1;
    }

    #pragma unroll
    for (int mt = 0; mt < 4; mt++) {
        const int row0 = Mbase + wm * 64 + mt * 16 + (lane >> 2);
        #pragma unroll
        for (int nt = 0; nt < 4; nt++) {
            const int col = Nbase + wn * 32 + nt * 8 + (lane & 3) * 2;
            if (col < Nout) {
                float2 v0 = make_float2(acc[mt][nt][0], acc[mt][nt][1]);
                float2 v1 = make_float2(acc[mt][nt][2], acc[mt][nt][3]);
                *reinterpret_cast<float2*>(C + (size_t)row0 * ldc + col) = v0;
                *reinterpret_cast<float2*>(C + (size_t)(row0 + 8) * ldc + col) = v1;
            }
        }
    }
}

// ================= conversions =================
__global__ void convert_split(const float4* __restrict__ in,
                              __nv_bfloat16* __restrict__ hi,
                              __nv_bfloat16* __restrict__ lo, int n4)
{
    int i = blockIdx.x * blockDim.x + threadIdx.x;
    if (i >= n4) return;
    float4 v = in[i];
    __nv_bfloat16 h[4], l[4];
    float f[4] = {v.x, v.y, v.z, v.w};
    #pragma unroll
    for (int j = 0; j < 4; j++) {
        h[j] = __float2bfloat16(f[j]);
        l[j] = __float2bfloat16(f[j] - __bfloat162float(h[j]));
    }
    *reinterpret_cast<uint2*>(hi + (size_t)i * 4) = *reinterpret_cast<uint2*>(h);
    *reinterpret_cast<uint2*>(lo + (size_t)i * 4) = *reinterpret_cast<uint2*>(l);
}

__global__ __launch_bounds__(256) void transpose_split(
    const float* __restrict__ W, int K, int N,
    __nv_bfloat16* __restrict__ Thi, __nv_bfloat16* __restrict__ Tlo)
{
    __shared__ float t[32][33];
    const int n0 = blockIdx.x * 32, k0 = blockIdx.y * 32;
    const int tx = threadIdx.x & 31, ty = threadIdx.x >> 5;
    #pragma unroll
    for (int j = 0; j < 4; j++) {
        int k = k0 + ty + j * 8;
        int n = n0 + tx;
        t[ty + j * 8][tx] = (n < N) ? W[(size_t)k * N + n] : 0.f;
    }
    __syncthreads();
    #pragma unroll
    for (int j = 0; j < 4; j++) {
        int n = n0 + ty + j * 8;
        int k = k0 + tx;
        float v = t[tx][ty + j * 8];
        __nv_bfloat16 h = __float2bfloat16(v);
        Thi[(size_t)n * K + k] = h;
        Tlo[(size_t)n * K + k] = __float2bfloat16(v - __bfloat162float(h));
    }
}

// ---------------- dt / dA precompute ----------------
__global__ void prep_dt(const float* __restrict__ zx,
                        const float* __restrict__ dt_bias,
                        const float* __restrict__ A_log,
                        float* __restrict__ dt_out,
                        float* __restrict__ dA_out)
{
    int idx = blockIdx.x * blockDim.x + threadIdx.x;
    if (idx >= ROWS * NHEADS) return;
    int h = idx & (NHEADS - 1);
    int row = idx >> 5;
    float v = zx[(size_t)row * D_IN_PROJ + (D_IN_PROJ - NHEADS) + h] + dt_bias[h];
    float dt = (v > 0.f) ? (v + log1pf(expf(-v))) : log1pf(expf(v));
    float A = -expf(A_log[h]);
    dt_out[idx] = dt;
    dA_out[idx] = expf(dt * A);
}

// ---------------- depthwise causal conv1d + SiLU (coalesced float4) ----------------
__global__ __launch_bounds__(256) void conv_silu2(
    const float* __restrict__ zx,
    const float* __restrict__ conv_w,
    const float* __restrict__ conv_b,
    float* __restrict__ out)
{
    const int row = blockIdx.x;
    const int l   = row & (SEQLEN - 1);
    const float* base = zx + (size_t)row * D_IN_PROJ + D_INNER;
    float* orow = out + (size_t)row * CONV_DIM;

    for (int c4 = threadIdx.x; c4 < CONV_DIM / 4; c4 += 256) {
        const int c = c4 * 4;
        float4 acc = *reinterpret_cast<const float4*>(conv_b + c);
        #pragma unroll
        for (int k = 0; k < D_CONV; k++) {
            int dl = l - (D_CONV - 1) + k;
            if (dl >= 0) {
                float4 w = *reinterpret_cast<const float4*>(conv_w + k * CONV_DIM + c);
                float4 v = *reinterpret_cast<const float4*>(
                    base + (long)(k - (D_CONV - 1)) * D_IN_PROJ + c);
                acc.x = fmaf(w.x, v.x, acc.x);
                acc.y = fmaf(w.y, v.y, acc.y);
                acc.z = fmaf(w.z, v.z, acc.z);
                acc.w = fmaf(w.w, v.w, acc.w);
            }
        }
        acc.x = acc.x / (1.f + expf(-acc.x));
        acc.y = acc.y / (1.f + expf(-acc.y));
        acc.z = acc.z / (1.f + expf(-acc.z));
        acc.w = acc.w / (1.f + expf(-acc.w));
        *reinterpret_cast<float4*>(orow + c) = acc;
    }
}

// ---------------- selective scan: 256 threads, chunked, sync-free inner loop ----------------
#define CH 8
__global__ __launch_bounds__(256) void ssm_scan3(
    const float* __restrict__ conv, const float* __restrict__ dtv,
    const float* __restrict__ dAv, const float* __restrict__ Dparm,
    float* __restrict__ y)
{
    const int b = blockIdx.x >> 5;
    const int h = blockIdx.x & 31;
    const int tid = threadIdx.x;
    const int p = tid & 63;
    const int g = tid >> 6;           // 0..3, states [g*16, g*16+16)
    const int nb = g * 16;

    __shared__ __align__(16) float sx[2][CH][64];
    __shared__ __align__(16) float sB[2][CH][64];
    __shared__ __align__(16) float sC[2][CH][64];
    __shared__ float sdt[2][CH], sdA[2][CH];
    __shared__ __align__(16) float sacc[CH][256];

    float st[16];
    #pragma unroll
    for (int i = 0; i < 16; i++) st[i] = 0.f;
    const float Dh = Dparm[h];
    const size_t rowbase = (size_t)b * SEQLEN;

    auto g_ptr = [&](int slot, int chunk) -> const float* {
        int l8 = slot / 48; int rem = slot % 48; int a = rem >> 4; int q = rem & 15;
        size_t row = rowbase + (size_t)chunk * CH + l8;
        int off = (a == 0) ? h * HEADDIM : (a == 1) ? D_INNER : (D_INNER + D_STATE);
        return conv + row * CONV_DIM + off + q * 4;
    };
    auto s_ptr = [&](int slot, int buf) -> float* {
        int l8 = slot / 48; int rem = slot % 48; int a = rem >> 4; int q = rem & 15;
        float* base = (a == 0) ? &sx[buf][l8][0] : (a == 1) ? &sB[buf][l8][0] : &sC[buf][l8][0];
        return base + q * 4;
    };

    // preload chunk 0
    {
        float4 v0 = *reinterpret_cast<const float4*>(g_ptr(tid, 0));
        *reinterpret_cast<float4*>(s_ptr(tid, 0)) = v0;
        if (tid < 128) {
            float4 v1 = *reinterpret_cast<const float4*>(g_ptr(tid + 256, 0));
            *reinterpret_cast<float4*>(s_ptr(tid + 256, 0)) = v1;
        }
        if (tid < 16) {
            int l8 = tid >> 1;
            size_t row = rowbase + l8;
            if (tid & 1) sdA[0][l8] = dAv[row * NHEADS + h];
            else         sdt[0][l8] = dtv[row * NHEADS + h];
        }
        __syncthreads();
    }

    const int NCHUNK = SEQLEN / CH;
    for (int c = 0; c < NCHUNK; c++) {
        const int buf = c & 1;
        float4 v0, v1; float sval = 0.f;
        const bool more = (c + 1 < NCHUNK);
        if (more) {
            v0 = *reinterpret_cast<const float4*>(g_ptr(tid, c + 1));
            if (tid < 128) v1 = *reinterpret_cast<const float4*>(g_ptr(tid + 256, c + 1));
            if (tid < 16) {
                int l8 = tid >> 1;
                size_t row = rowbase + (size_t)(c + 1) * CH + l8;
                sval = (tid & 1) ? dAv[row * NHEADS + h] : dtv[row * NHEADS + h];
            }
        }
        #pragma unroll
        for (int l = 0; l < CH; l++) {
            const float dt_t = sdt[buf][l];
            const float dA_t = sdA[buf][l];
            const float dtx  = dt_t * sx[buf][l][p];
            const float4* Bp = reinterpret_cast<const float4*>(&sB[buf][l][nb]);
            const float4* Cp = reinterpret_cast<const float4*>(&sC[buf][l][nb]);
            float a0 = 0.f, a1 = 0.f;
            #pragma unroll
            for (int i4 = 0; i4 < 4; i4++) {
                float4 Bv = Bp[i4];
                float4 Cv = Cp[i4];
                st[i4*4+0] = fmaf(st[i4*4+0], dA_t, dtx * Bv.x); a0 = fmaf(st[i4*4+0], Cv.x, a0);
                st[i4*4+1] = fmaf(st[i4*4+1], dA_t, dtx * Bv.y); a1 = fmaf(st[i4*4+1], Cv.y, a1);
                st[i4*4+2] = fmaf(st[i4*4+2], dA_t, dtx * Bv.z); a0 = fmaf(st[i4*4+2], Cv.z, a0);
                st[i4*4+3] = fmaf(st[i4*4+3], dA_t, dtx * Bv.w); a1 = fmaf(st[i4*4+3], Cv.w, a1);
            }
            sacc[l][tid] = a0 + a1;
        }
        __syncthreads();
        #pragma unroll
        for (int j = 0; j < 2; j++) {
            int idx = tid + j * 256;
            int l = idx >> 6, pp = idx & 63;
            float yv = sacc[l][pp] + sacc[l][pp + 64] + sacc[l][pp + 128] + sacc[l][pp + 192]
                     + Dh * sx[buf][l][pp];
            y[(rowbase + (size_t)c * CH + l) * D_INNER + h * HEADDIM + pp] = yv;
        }
        if (more) {
            *reinterpret_cast<float4*>(s_ptr(tid, buf ^ 1)) = v0;
            if (tid < 128) *reinterpret_cast<float4*>(s_ptr(tid + 256, buf ^ 1)) = v1;
            if (tid < 16) {
                int l8 = tid >> 1;
                if (tid & 1) sdA[buf ^ 1][l8] = sval;
                else         sdt[buf ^ 1][l8] = sval;
            }
        }
        __syncthreads();
    }
}

// ---------------- gate (y * silu(z)) + RMSNorm -> bf16 hi/lo ----------------
__global__ __launch_bounds__(256) void gate_rmsnorm(
    const float* __restrict__ yraw,
    const float* __restrict__ zx,
    const float* __restrict__ norm_w,
    __nv_bfloat16* __restrict__ out_hi,
    __nv_bfloat16* __restrict__ out_lo)
{
    const int row = blockIdx.x;
    const int tid = threadIdx.x;
    const float* yr = yraw + (size_t)row * D_INNER;
    const float* z  = zx + (size_t)row * D_IN_PROJ;

    float v[8];
    float ss = 0.f;
    #pragma unroll
    for (int i = 0; i < 8; i++) {
        int c = tid + i * 256;
        float zz = z[c];
        float g  = zz / (1.f + expf(-zz));
        float t  = yr[c] * g;
        v[i] = t;
        ss = fmaf(t, t, ss);
    }
    #pragma unroll
    for (int off = 16; off > 0; off >>= 1)
        ss += __shfl_xor_sync(0xffffffffu, ss, off);
    __shared__ float swarp[8];
    __shared__ float stot;
    if ((tid & 31) == 0) swarp[tid >> 5] = ss;
    __syncthreads();
    if (tid == 0) {
        float t = 0.f;
        #pragma unroll
        for (int i = 0; i < 8; i++) t += swarp[i];
        stot = t;
    }
    __syncthreads();
    const float scale = rsqrtf(stot * (1.f / D_INNER) + 1e-5f);
    #pragma unroll
    for (int i = 0; i < 8; i++) {
        int c = tid + i * 256;
        float t = v[i] * scale * norm_w[c];
        __nv_bfloat16 h = __float2bfloat16(t);
        out_hi[(size_t)row * D_INNER + c] = h;
        out_lo[(size_t)row * D_INNER + c] = __float2bfloat16(t - __bfloat162float(h));
    }
}

// ---------------- launcher ----------------
extern "C" void kernel_launch(void* const* d_in, const int* in_sizes, int n_in,
                              void* d_out, int out_size)
{
    const float* u       = (const float*)d_in[0];
    const float* W_in    = (const float*)d_in[1];
    const float* conv_w  = (const float*)d_in[2];
    const float* conv_b  = (const float*)d_in[3];
    const float* dt_bias = (const float*)d_in[4];
    const float* A_log   = (const float*)d_in[5];
    const float* Dp      = (const float*)d_in[6];
    const float* norm_w  = (const float*)d_in[7];
    const float* W_out   = (const float*)d_in[8];
    float* out = (float*)d_out;

    float *zx, *cv, *dtp, *dAp, *yp;
    __nv_bfloat16 *uhi, *ulo, *wih, *wil, *woh, *wol, *ynh, *ynl;
    cudaGetSymbolAddress((void**)&zx,  g_zx);
    cudaGetSymbolAddress((void**)&cv,  g_conv);
    cudaGetSymbolAddress((void**)&dtp, g_dt);
    cudaGetSymbolAddress((void**)&dAp, g_dA);
    cudaGetSymbolAddress((void**)&yp,  g_y);
    cudaGetSymbolAddress((void**)&uhi, g_u_hi);
    cudaGetSymbolAddress((void**)&ulo, g_u_lo);
    cudaGetSymbolAddress((void**)&wih, g_wint_hi);
    cudaGetSymbolAddress((void**)&wil, g_wint_lo);
    cudaGetSymbolAddress((void**)&woh, g_woutt_hi);
    cudaGetSymbolAddress((void**)&wol, g_woutt_lo);
    cudaGetSymbolAddress((void**)&ynh, g_yn_hi);
    cudaGetSymbolAddress((void**)&ynl, g_yn_lo);

    cudaFuncSetAttribute(gemm_mma, cudaFuncAttributeMaxDynamicSharedMemorySize, GEMM_SMEM);

    // operand prep
    {
        int n4 = ROWS * D_MODEL / 4;
        convert_split<<<(n4 + 255) / 256, 256>>>((const float4*)u, uhi, ulo, n4);
    }
    transpose_split<<<dim3(NP1 / 32, D_MODEL / 32), 256>>>(W_in, D_MODEL, D_IN_PROJ, wih, wil);
    transpose_split<<<dim3(D_MODEL / 32, D_INNER / 32), 256>>>(W_out, D_INNER, D_MODEL, woh, wol);

    // 1) zxbcdt = u @ W_in
    gemm_mma<<<dim3(NP1 / 128, ROWS / 128), 256, GEMM_SMEM>>>(
        uhi, ulo, wih, wil, zx, D_MODEL, D_IN_PROJ, D_IN_PROJ);

    // 2) dt / dA
    prep_dt<<<(ROWS * NHEADS + 255) / 256, 256>>>(zx, dt_bias, A_log, dtp, dAp);
    // 3) depthwise conv + silu
    conv_silu2<<<ROWS, 256>>>(zx, conv_w, conv_b, cv);
    // 4) selective scan (+ x*D)
    ssm_scan3<<<B_SZ * NHEADS, 256>>>(cv, dtp, dAp, Dp, yp);
    // 5) gate + rmsnorm -> bf16 hi/lo
    gate_rmsnorm<<<ROWS, 256>>>(yp, zx, norm_w, ynh, ynl);
    // 6) out = yn @ W_out
    gemm_mma<<<dim3(D_MODEL / 128, ROWS / 128), 256, GEMM_SMEM>>>(
        ynh, ynl, woh, wol, out, D_INNER, D_MODEL, D_MODEL);
}